// round 4
// baseline (speedup 1.0000x reference)
#include <cuda_runtime.h>
#include <cuda_bf16.h>
#include <cstdint>
#include <math.h>

// ============================================================================
// Aligner: out = softmax((ix@W^T+b) @ (io@W^T+b)^T) @ io
// B=8, L=2048, D=1024, fp32 in/out.
// Round 4: HMMA split-precision GEMM, warp tile 64x64 (CTA 128x256),
// 3-stage cp.async pipeline, one __syncthreads per K-chunk.
// ============================================================================

#define BATCH 8
#define LSEQ  2048
#define DIM   1024
#define MELEMS ((size_t)BATCH * LSEQ * DIM)
#define SELEMS ((size_t)BATCH * LSEQ * LSEQ)

// ---- scratch (__device__ globals per allocation rules) ----
__device__ __nv_bfloat16 g_ix_hi[MELEMS],  g_ix_lo[MELEMS];
__device__ __nv_bfloat16 g_io_hi[MELEMS],  g_io_lo[MELEMS];
__device__ __nv_bfloat16 g_ioT_hi[MELEMS], g_ioT_lo[MELEMS];
__device__ __nv_bfloat16 g_ex_hi[MELEMS],  g_ex_lo[MELEMS];
__device__ __nv_bfloat16 g_eo_hi[MELEMS],  g_eo_lo[MELEMS];
__device__ __nv_bfloat16 g_w_hi[DIM * DIM], g_w_lo[DIM * DIM];
__device__ float         g_s[SELEMS];
__device__ __nv_bfloat16 g_p_hi[SELEMS],   g_p_lo[SELEMS];

// ============================================================================
// PTX helpers (portable only)
// ============================================================================
__device__ __forceinline__ uint32_t smem_u32(const void* p) {
    uint32_t a;
    asm("{ .reg .u64 t; cvta.to.shared.u64 t, %1; cvt.u32.u64 %0, t; }"
        : "=r"(a) : "l"(p));
    return a;
}

#define CP_COMMIT() asm volatile("cp.async.commit_group;" ::: "memory")
#define CP_WAIT(N)  asm volatile("cp.async.wait_group %0;" :: "n"(N) : "memory")

__device__ __forceinline__ void cp16(uint32_t dst, const void* src) {
    asm volatile("cp.async.cg.shared.global [%0], [%1], 16;" :: "r"(dst), "l"(src));
}

__device__ __forceinline__ void ldsm4(uint32_t* r, uint32_t addr) {
    asm volatile("ldmatrix.sync.aligned.m8n8.x4.shared.b16 {%0,%1,%2,%3}, [%4];"
                 : "=r"(r[0]), "=r"(r[1]), "=r"(r[2]), "=r"(r[3]) : "r"(addr));
}

__device__ __forceinline__ void mma16816(float* d, const uint32_t* a,
                                         const uint32_t* b) {
    asm volatile(
        "mma.sync.aligned.m16n8k16.row.col.f32.bf16.bf16.f32 "
        "{%0,%1,%2,%3}, {%4,%5,%6,%7}, {%8,%9}, {%0,%1,%2,%3};"
        : "+f"(d[0]), "+f"(d[1]), "+f"(d[2]), "+f"(d[3])
        : "r"(a[0]), "r"(a[1]), "r"(a[2]), "r"(a[3]), "r"(b[0]), "r"(b[1]));
}

// tile layout: [rows][64 bytes], 16B chunks swizzled: chunk ^ ((row>>1)&3)
__device__ __forceinline__ uint32_t tile_addr(uint32_t base, int row, int chunk) {
    return base + row * 64 + ((chunk ^ ((row >> 1) & 3)) << 4);
}

// ============================================================================
// Split / transpose / softmax helper kernels
// ============================================================================
__device__ __forceinline__ void split1(float v, __nv_bfloat16& h, __nv_bfloat16& l) {
    h = __float2bfloat16(v);
    l = __float2bfloat16(v - __bfloat162float(h));
}

__global__ void split_f32(const float* __restrict__ s,
                          __nv_bfloat16* __restrict__ hi,
                          __nv_bfloat16* __restrict__ lo, size_t n) {
    size_t i = ((size_t)blockIdx.x * blockDim.x + threadIdx.x) * 4;
    if (i >= n) return;
    float4 v = *(const float4*)(s + i);
    __nv_bfloat16 h0, h1, h2, h3, l0, l1, l2, l3;
    split1(v.x, h0, l0); split1(v.y, h1, l1);
    split1(v.z, h2, l2); split1(v.w, h3, l3);
    *(__nv_bfloat162*)(hi + i)     = __nv_bfloat162(h0, h1);
    *(__nv_bfloat162*)(hi + i + 2) = __nv_bfloat162(h2, h3);
    *(__nv_bfloat162*)(lo + i)     = __nv_bfloat162(l0, l1);
    *(__nv_bfloat162*)(lo + i + 2) = __nv_bfloat162(l2, l3);
}

__global__ void transpose_split(const float* __restrict__ src,
                                __nv_bfloat16* __restrict__ hiT,
                                __nv_bfloat16* __restrict__ loT) {
    __shared__ float t[32][33];
    int b = blockIdx.z;
    int l0 = blockIdx.x * 32, d0 = blockIdx.y * 32;
    const float* s = src + (size_t)b * LSEQ * DIM;
    #pragma unroll
    for (int i = 0; i < 32; i += 8)
        t[threadIdx.y + i][threadIdx.x] =
            s[(size_t)(l0 + threadIdx.y + i) * DIM + d0 + threadIdx.x];
    __syncthreads();
    size_t ob = (size_t)b * DIM * LSEQ;
    #pragma unroll
    for (int i = 0; i < 32; i += 8) {
        float v = t[threadIdx.x][threadIdx.y + i];
        __nv_bfloat16 h, l;
        split1(v, h, l);
        size_t o = ob + (size_t)(d0 + threadIdx.y + i) * LSEQ + l0 + threadIdx.x;
        hiT[o] = h;
        loT[o] = l;
    }
}

__global__ void softmax_split(float* __restrict__ S,
                              __nv_bfloat16* __restrict__ phi,
                              __nv_bfloat16* __restrict__ plo, int cols) {
    float* row = S + (size_t)blockIdx.x * cols;
    __nv_bfloat16* hr = phi + (size_t)blockIdx.x * cols;
    __nv_bfloat16* lr = plo + (size_t)blockIdx.x * cols;
    const int tid = threadIdx.x;

    float lmax = -3.0e38f;
    for (int i = tid * 4; i < cols; i += 1024) {
        float4 v = *(const float4*)(row + i);
        lmax = fmaxf(lmax, fmaxf(fmaxf(v.x, v.y), fmaxf(v.z, v.w)));
    }
    #pragma unroll
    for (int o = 16; o; o >>= 1)
        lmax = fmaxf(lmax, __shfl_xor_sync(0xFFFFFFFFu, lmax, o));
    __shared__ float sm[8], ss[8];
    if ((tid & 31) == 0) sm[tid >> 5] = lmax;
    __syncthreads();
    float rmax = fmaxf(fmaxf(fmaxf(sm[0], sm[1]), fmaxf(sm[2], sm[3])),
                       fmaxf(fmaxf(sm[4], sm[5]), fmaxf(sm[6], sm[7])));

    float lsum = 0.f;
    for (int i = tid * 4; i < cols; i += 1024) {
        float4 v = *(const float4*)(row + i);
        v.x = expf(v.x - rmax); v.y = expf(v.y - rmax);
        v.z = expf(v.z - rmax); v.w = expf(v.w - rmax);
        *(float4*)(row + i) = v;
        lsum += v.x + v.y + v.z + v.w;
    }
    #pragma unroll
    for (int o = 16; o; o >>= 1)
        lsum += __shfl_xor_sync(0xFFFFFFFFu, lsum, o);
    if ((tid & 31) == 0) ss[tid >> 5] = lsum;
    __syncthreads();
    float inv = 1.f / (ss[0]+ss[1]+ss[2]+ss[3]+ss[4]+ss[5]+ss[6]+ss[7]);

    for (int i = tid * 4; i < cols; i += 1024) {
        float4 v = *(const float4*)(row + i);
        v.x *= inv; v.y *= inv; v.z *= inv; v.w *= inv;
        __nv_bfloat16 h0,h1,h2,h3,l0,l1,l2,l3;
        split1(v.x,h0,l0); split1(v.y,h1,l1); split1(v.z,h2,l2); split1(v.w,h3,l3);
        *(__nv_bfloat162*)(hr + i)     = __nv_bfloat162(h0, h1);
        *(__nv_bfloat162*)(hr + i + 2) = __nv_bfloat162(h2, h3);
        *(__nv_bfloat162*)(lr + i)     = __nv_bfloat162(l0, l1);
        *(__nv_bfloat162*)(lr + i + 2) = __nv_bfloat162(l2, l3);
    }
}

// ============================================================================
// Split-precision HMMA GEMM, CTA tile 128x256, warp tile 64x64, K-chunk 32.
// C[m,n] = sum_k (Ahi+Alo)[m,k]*(Bhi+Blo)[n,k]  (lo*lo dropped)
// smem per stage: Ahi/Alo [128x32] bf16 (8KB each) + Bhi/Blo [256x32] (16KB
// each) = 48KB; 3 stages = 144KB.
// ============================================================================
#define BKC 32
#define TA_B 8192
#define TB_B 16384
#define STAGE_B (2 * TA_B + 2 * TB_B)   // 49152
#define NSTAGE 3

__global__ __launch_bounds__(256, 1)
void gemm_split(const __nv_bfloat16* __restrict__ Ahi, const __nv_bfloat16* __restrict__ Alo,
                const __nv_bfloat16* __restrict__ Bhi, const __nv_bfloat16* __restrict__ Blo,
                float* __restrict__ Cf,
                __nv_bfloat16* __restrict__ Chi, __nv_bfloat16* __restrict__ Clo,
                const float* __restrict__ bias,
                int K, int N,
                long long sA, long long sB, long long sC)
{
    extern __shared__ __align__(128) char smem[];
    const uint32_t sb = smem_u32(smem);

    const int tid  = threadIdx.x;
    const int wid  = tid >> 5;
    const int lane = tid & 31;
    const int wm   = wid >> 2;       // 0..1 (64 rows)
    const int wn   = wid & 3;        // 0..3 (64 cols)

    const long long bz = blockIdx.z;
    const long long m0 = (long long)blockIdx.y * 128;
    const long long n0 = (long long)blockIdx.x * 256;

    const __nv_bfloat16* srcA[2] = { Ahi + bz * sA + m0 * K,
                                     Alo + bz * sA + m0 * K };
    const __nv_bfloat16* srcB[2] = { Bhi + bz * sB + n0 * K,
                                     Blo + bz * sB + n0 * K };

    auto load_chunk = [&](int stage, int k0) {
        const uint32_t base = sb + stage * STAGE_B;
        #pragma unroll
        for (int t = 0; t < 2; ++t) {
            #pragma unroll
            for (int j = 0; j < 2; ++j) {           // A tiles: 512 cp16 each
                int idx = tid * 2 + j;
                int row = idx >> 2, ch = idx & 3;
                cp16(tile_addr(base + t * TA_B, row, ch),
                     srcA[t] + (long long)row * K + k0 + ch * 8);
            }
        }
        #pragma unroll
        for (int t = 0; t < 2; ++t) {
            #pragma unroll
            for (int j = 0; j < 4; ++j) {           // B tiles: 1024 cp16 each
                int idx = tid * 4 + j;
                int row = idx >> 2, ch = idx & 3;
                cp16(tile_addr(base + 2 * TA_B + t * TB_B, row, ch),
                     srcB[t] + (long long)row * K + k0 + ch * 8);
            }
        }
        CP_COMMIT();
    };

    float acc[4][8][4];
    #pragma unroll
    for (int i = 0; i < 4; ++i)
        #pragma unroll
        for (int j = 0; j < 8; ++j)
            #pragma unroll
            for (int e = 0; e < 4; ++e) acc[i][j][e] = 0.f;

    const int NC = K >> 5;
    load_chunk(0, 0);
    load_chunk(1, BKC);

    const int lrow = lane & 15;
    const int lch  = lane >> 4;

    for (int c = 0; c < NC; ++c) {
        if (c + 1 < NC) CP_WAIT(1); else CP_WAIT(0);
        __syncthreads();
        if (c + 2 < NC) load_chunk((c + 2) % NSTAGE, (c + 2) * BKC);

        const uint32_t st  = sb + (c % NSTAGE) * STAGE_B;
        const uint32_t sAh = st;
        const uint32_t sAl = st + TA_B;
        const uint32_t sBh = st + 2 * TA_B;
        const uint32_t sBl = st + 2 * TA_B + TB_B;

        #pragma unroll
        for (int ks = 0; ks < 2; ++ks) {
            const int chunk = ks * 2 + lch;
            uint32_t ahi[4][4], alo[4][4];
            #pragma unroll
            for (int mi = 0; mi < 4; ++mi) {
                const int row = wm * 64 + mi * 16 + lrow;
                ldsm4(ahi[mi], tile_addr(sAh, row, chunk));
                ldsm4(alo[mi], tile_addr(sAl, row, chunk));
            }
            #pragma unroll
            for (int h = 0; h < 2; ++h) {
                uint32_t bhi[4][2], blo[4][2];
                #pragma unroll
                for (int bi = 0; bi < 2; ++bi) {
                    const int row = wn * 64 + h * 32 + bi * 16 + lrow;
                    uint32_t t4[4];
                    ldsm4(t4, tile_addr(sBh, row, chunk));
                    bhi[bi*2][0]   = t4[0]; bhi[bi*2][1]   = t4[2];
                    bhi[bi*2+1][0] = t4[1]; bhi[bi*2+1][1] = t4[3];
                    ldsm4(t4, tile_addr(sBl, row, chunk));
                    blo[bi*2][0]   = t4[0]; blo[bi*2][1]   = t4[2];
                    blo[bi*2+1][0] = t4[1]; blo[bi*2+1][1] = t4[3];
                }
                #pragma unroll
                for (int mi = 0; mi < 4; ++mi)
                    #pragma unroll
                    for (int ni = 0; ni < 4; ++ni) {
                        float* a4 = acc[mi][h * 4 + ni];
                        mma16816(a4, ahi[mi], bhi[ni]);
                        mma16816(a4, ahi[mi], blo[ni]);
                        mma16816(a4, alo[mi], bhi[ni]);
                    }
            }
        }
        __syncthreads();
    }

    // ---- epilogue ----
    const int r1 = lane >> 2;
    const int c0 = (lane & 3) * 2;
    #pragma unroll
    for (int mi = 0; mi < 4; ++mi) {
        #pragma unroll
        for (int j = 0; j < 8; ++j) {
            const long long gm = m0 + wm * 64 + mi * 16 + r1;
            const long long gn = n0 + wn * 64 + (j >> 2) * 32 + (j & 3) * 8 + c0;
            float v0 = acc[mi][j][0], v1 = acc[mi][j][1];
            float v2 = acc[mi][j][2], v3 = acc[mi][j][3];
            if (bias) {
                float b0 = bias[gn], b1 = bias[gn + 1];
                v0 += b0; v1 += b1; v2 += b0; v3 += b1;
            }
            if (Cf) {
                float* d0 = Cf + bz * sC + gm * N + gn;
                float* d1 = Cf + bz * sC + (gm + 8) * N + gn;
                d0[0] = v0; d0[1] = v1;
                d1[0] = v2; d1[1] = v3;
            } else {
                __nv_bfloat16 h0, h1, h2, h3, l0, l1, l2, l3;
                split1(v0, h0, l0); split1(v1, h1, l1);
                split1(v2, h2, l2); split1(v3, h3, l3);
                *(__nv_bfloat162*)(Chi + bz * sC + gm * N + gn)       = __nv_bfloat162(h0, h1);
                *(__nv_bfloat162*)(Clo + bz * sC + gm * N + gn)       = __nv_bfloat162(l0, l1);
                *(__nv_bfloat162*)(Chi + bz * sC + (gm + 8) * N + gn) = __nv_bfloat162(h2, h3);
                *(__nv_bfloat162*)(Clo + bz * sC + (gm + 8) * N + gn) = __nv_bfloat162(l2, l3);
            }
        }
    }
}

// ============================================================================
extern "C" void kernel_launch(void* const* d_in, const int* in_sizes, int n_in,
                              void* d_out, int out_size)
{
    const float* ix = (const float*)d_in[0];
    const float* io = (const float*)d_in[1];
    const float* W  = (const float*)d_in[2];
    const float* bb = (const float*)d_in[3];
    float* out = (float*)d_out;

    __nv_bfloat16 *ix_hi, *ix_lo, *io_hi, *io_lo, *ioT_hi, *ioT_lo;
    __nv_bfloat16 *ex_hi, *ex_lo, *eo_hi, *eo_lo, *w_hi, *w_lo, *p_hi, *p_lo;
    float* s;
    cudaGetSymbolAddress((void**)&ix_hi, g_ix_hi);
    cudaGetSymbolAddress((void**)&ix_lo, g_ix_lo);
    cudaGetSymbolAddress((void**)&io_hi, g_io_hi);
    cudaGetSymbolAddress((void**)&io_lo, g_io_lo);
    cudaGetSymbolAddress((void**)&ioT_hi, g_ioT_hi);
    cudaGetSymbolAddress((void**)&ioT_lo, g_ioT_lo);
    cudaGetSymbolAddress((void**)&ex_hi, g_ex_hi);
    cudaGetSymbolAddress((void**)&ex_lo, g_ex_lo);
    cudaGetSymbolAddress((void**)&eo_hi, g_eo_hi);
    cudaGetSymbolAddress((void**)&eo_lo, g_eo_lo);
    cudaGetSymbolAddress((void**)&w_hi, g_w_hi);
    cudaGetSymbolAddress((void**)&w_lo, g_w_lo);
    cudaGetSymbolAddress((void**)&p_hi, g_p_hi);
    cudaGetSymbolAddress((void**)&p_lo, g_p_lo);
    cudaGetSymbolAddress((void**)&s, g_s);

    static bool attr_set = false;
    const int smem_bytes = NSTAGE * STAGE_B;  // 144 KB
    if (!attr_set) {
        cudaFuncSetAttribute(gemm_split,
                             cudaFuncAttributeMaxDynamicSharedMemorySize, smem_bytes);
        attr_set = true;
    }

    // 1) splits
    split_f32<<<(unsigned)(MELEMS / 4 / 256), 256>>>(ix, ix_hi, ix_lo, MELEMS);
    split_f32<<<(unsigned)(MELEMS / 4 / 256), 256>>>(io, io_hi, io_lo, MELEMS);
    split_f32<<<(DIM * DIM) / 4 / 256, 256>>>(W, w_hi, w_lo, (size_t)DIM * DIM);
    transpose_split<<<dim3(LSEQ / 32, DIM / 32, BATCH), dim3(32, 8)>>>(io, ioT_hi, ioT_lo);

    // 2) projections: E = X @ W^T + b -> bf16 split (M=16384, N=1024, K=1024)
    {
        dim3 g(DIM / 256, (BATCH * LSEQ) / 128, 1);
        gemm_split<<<g, 256, smem_bytes>>>(ix_hi, ix_lo, w_hi, w_lo,
                                           nullptr, ex_hi, ex_lo, bb,
                                           DIM, DIM, 0, 0, 0);
        gemm_split<<<g, 256, smem_bytes>>>(io_hi, io_lo, w_hi, w_lo,
                                           nullptr, eo_hi, eo_lo, bb,
                                           DIM, DIM, 0, 0, 0);
    }

    // 3) scores: S[b] = Ex[b] @ Eo[b]^T -> fp32 (M=N=2048, K=1024)
    {
        dim3 g(LSEQ / 256, LSEQ / 128, BATCH);
        gemm_split<<<g, 256, smem_bytes>>>(ex_hi, ex_lo, eo_hi, eo_lo,
                                           s, nullptr, nullptr, nullptr,
                                           DIM, LSEQ,
                                           (long long)LSEQ * DIM,
                                           (long long)LSEQ * DIM,
                                           (long long)LSEQ * LSEQ);
    }

    // 4) softmax -> P bf16 split
    softmax_split<<<BATCH * LSEQ, 256>>>(s, p_hi, p_lo, LSEQ);

    // 5) out[b] = P[b] @ ioT[b]^T -> fp32 d_out (M=2048, N=1024, K=2048)
    {
        dim3 g(DIM / 256, LSEQ / 128, BATCH);
        gemm_split<<<g, 256, smem_bytes>>>(p_hi, p_lo, ioT_hi, ioT_lo,
                                           out, nullptr, nullptr, nullptr,
                                           LSEQ, DIM,
                                           (long long)LSEQ * LSEQ,
                                           (long long)DIM * LSEQ,
                                           (long long)LSEQ * DIM);
    }
}

// round 5
// speedup vs baseline: 1.2738x; 1.2738x over previous
#include <cuda_runtime.h>
#include <cuda_bf16.h>
#include <cstdint>
#include <math.h>

// ============================================================================
// Aligner: out = softmax((ix@W^T+b) @ (io@W^T+b)^T) @ io
// B=8, L=2048, D=1024, fp32 in/out.
// Round 5: R3 GEMM config (CTA 128x128, warp 64x32) + 3-stage cp.async ring
// (prefetch depth 2) + 2 CTAs/SM occupancy. 3-pass split precision unchanged.
// ============================================================================

#define BATCH 8
#define LSEQ  2048
#define DIM   1024
#define MELEMS ((size_t)BATCH * LSEQ * DIM)
#define SELEMS ((size_t)BATCH * LSEQ * LSEQ)

// ---- scratch (__device__ globals per allocation rules) ----
__device__ __nv_bfloat16 g_ix_hi[MELEMS],  g_ix_lo[MELEMS];
__device__ __nv_bfloat16 g_io_hi[MELEMS],  g_io_lo[MELEMS];
__device__ __nv_bfloat16 g_ioT_hi[MELEMS], g_ioT_lo[MELEMS];
__device__ __nv_bfloat16 g_ex_hi[MELEMS],  g_ex_lo[MELEMS];
__device__ __nv_bfloat16 g_eo_hi[MELEMS],  g_eo_lo[MELEMS];
__device__ __nv_bfloat16 g_w_hi[DIM * DIM], g_w_lo[DIM * DIM];
__device__ float         g_s[SELEMS];
__device__ __nv_bfloat16 g_p_hi[SELEMS],   g_p_lo[SELEMS];

// ============================================================================
// PTX helpers (portable only)
// ============================================================================
__device__ __forceinline__ uint32_t smem_u32(const void* p) {
    uint32_t a;
    asm("{ .reg .u64 t; cvta.to.shared.u64 t, %1; cvt.u32.u64 %0, t; }"
        : "=r"(a) : "l"(p));
    return a;
}

#define CP_COMMIT() asm volatile("cp.async.commit_group;" ::: "memory")
#define CP_WAIT(N)  asm volatile("cp.async.wait_group %0;" :: "n"(N) : "memory")

__device__ __forceinline__ void cp16(uint32_t dst, const void* src) {
    asm volatile("cp.async.cg.shared.global [%0], [%1], 16;" :: "r"(dst), "l"(src));
}

__device__ __forceinline__ void ldsm4(uint32_t* r, uint32_t addr) {
    asm volatile("ldmatrix.sync.aligned.m8n8.x4.shared.b16 {%0,%1,%2,%3}, [%4];"
                 : "=r"(r[0]), "=r"(r[1]), "=r"(r[2]), "=r"(r[3]) : "r"(addr));
}

__device__ __forceinline__ void mma16816(float* d, const uint32_t* a,
                                         const uint32_t* b) {
    asm volatile(
        "mma.sync.aligned.m16n8k16.row.col.f32.bf16.bf16.f32 "
        "{%0,%1,%2,%3}, {%4,%5,%6,%7}, {%8,%9}, {%0,%1,%2,%3};"
        : "+f"(d[0]), "+f"(d[1]), "+f"(d[2]), "+f"(d[3])
        : "r"(a[0]), "r"(a[1]), "r"(a[2]), "r"(a[3]), "r"(b[0]), "r"(b[1]));
}

// tile layout: [rows][64 bytes], 16B chunks swizzled: chunk ^ ((row>>1)&3)
__device__ __forceinline__ uint32_t tile_addr(uint32_t base, int row, int chunk) {
    return base + row * 64 + ((chunk ^ ((row >> 1) & 3)) << 4);
}

// ============================================================================
// Split / transpose / softmax helper kernels
// ============================================================================
__device__ __forceinline__ void split1(float v, __nv_bfloat16& h, __nv_bfloat16& l) {
    h = __float2bfloat16(v);
    l = __float2bfloat16(v - __bfloat162float(h));
}

__global__ void split_f32(const float* __restrict__ s,
                          __nv_bfloat16* __restrict__ hi,
                          __nv_bfloat16* __restrict__ lo, size_t n) {
    size_t i = ((size_t)blockIdx.x * blockDim.x + threadIdx.x) * 4;
    if (i >= n) return;
    float4 v = *(const float4*)(s + i);
    __nv_bfloat16 h0, h1, h2, h3, l0, l1, l2, l3;
    split1(v.x, h0, l0); split1(v.y, h1, l1);
    split1(v.z, h2, l2); split1(v.w, h3, l3);
    *(__nv_bfloat162*)(hi + i)     = __nv_bfloat162(h0, h1);
    *(__nv_bfloat162*)(hi + i + 2) = __nv_bfloat162(h2, h3);
    *(__nv_bfloat162*)(lo + i)     = __nv_bfloat162(l0, l1);
    *(__nv_bfloat162*)(lo + i + 2) = __nv_bfloat162(l2, l3);
}

__global__ void transpose_split(const float* __restrict__ src,
                                __nv_bfloat16* __restrict__ hiT,
                                __nv_bfloat16* __restrict__ loT) {
    __shared__ float t[32][33];
    int b = blockIdx.z;
    int l0 = blockIdx.x * 32, d0 = blockIdx.y * 32;
    const float* s = src + (size_t)b * LSEQ * DIM;
    #pragma unroll
    for (int i = 0; i < 32; i += 8)
        t[threadIdx.y + i][threadIdx.x] =
            s[(size_t)(l0 + threadIdx.y + i) * DIM + d0 + threadIdx.x];
    __syncthreads();
    size_t ob = (size_t)b * DIM * LSEQ;
    #pragma unroll
    for (int i = 0; i < 32; i += 8) {
        float v = t[threadIdx.x][threadIdx.y + i];
        __nv_bfloat16 h, l;
        split1(v, h, l);
        size_t o = ob + (size_t)(d0 + threadIdx.y + i) * LSEQ + l0 + threadIdx.x;
        hiT[o] = h;
        loT[o] = l;
    }
}

__global__ void softmax_split(float* __restrict__ S,
                              __nv_bfloat16* __restrict__ phi,
                              __nv_bfloat16* __restrict__ plo, int cols) {
    float* row = S + (size_t)blockIdx.x * cols;
    __nv_bfloat16* hr = phi + (size_t)blockIdx.x * cols;
    __nv_bfloat16* lr = plo + (size_t)blockIdx.x * cols;
    const int tid = threadIdx.x;

    float lmax = -3.0e38f;
    for (int i = tid * 4; i < cols; i += 1024) {
        float4 v = *(const float4*)(row + i);
        lmax = fmaxf(lmax, fmaxf(fmaxf(v.x, v.y), fmaxf(v.z, v.w)));
    }
    #pragma unroll
    for (int o = 16; o; o >>= 1)
        lmax = fmaxf(lmax, __shfl_xor_sync(0xFFFFFFFFu, lmax, o));
    __shared__ float sm[8], ss[8];
    if ((tid & 31) == 0) sm[tid >> 5] = lmax;
    __syncthreads();
    float rmax = fmaxf(fmaxf(fmaxf(sm[0], sm[1]), fmaxf(sm[2], sm[3])),
                       fmaxf(fmaxf(sm[4], sm[5]), fmaxf(sm[6], sm[7])));

    float lsum = 0.f;
    for (int i = tid * 4; i < cols; i += 1024) {
        float4 v = *(const float4*)(row + i);
        v.x = expf(v.x - rmax); v.y = expf(v.y - rmax);
        v.z = expf(v.z - rmax); v.w = expf(v.w - rmax);
        *(float4*)(row + i) = v;
        lsum += v.x + v.y + v.z + v.w;
    }
    #pragma unroll
    for (int o = 16; o; o >>= 1)
        lsum += __shfl_xor_sync(0xFFFFFFFFu, lsum, o);
    if ((tid & 31) == 0) ss[tid >> 5] = lsum;
    __syncthreads();
    float inv = 1.f / (ss[0]+ss[1]+ss[2]+ss[3]+ss[4]+ss[5]+ss[6]+ss[7]);

    for (int i = tid * 4; i < cols; i += 1024) {
        float4 v = *(const float4*)(row + i);
        v.x *= inv; v.y *= inv; v.z *= inv; v.w *= inv;
        __nv_bfloat16 h0,h1,h2,h3,l0,l1,l2,l3;
        split1(v.x,h0,l0); split1(v.y,h1,l1); split1(v.z,h2,l2); split1(v.w,h3,l3);
        *(__nv_bfloat162*)(hr + i)     = __nv_bfloat162(h0, h1);
        *(__nv_bfloat162*)(hr + i + 2) = __nv_bfloat162(h2, h3);
        *(__nv_bfloat162*)(lr + i)     = __nv_bfloat162(l0, l1);
        *(__nv_bfloat162*)(lr + i + 2) = __nv_bfloat162(l2, l3);
    }
}

// ============================================================================
// Split-precision HMMA GEMM, CTA 128x128, warp tile 64x32, K-chunk 32.
// 3 smem stages (prefetch depth 2), target 2 CTAs/SM.
// ============================================================================
#define BKC 32
#define TILE_B 8192
#define STAGE_B (4 * TILE_B)     // 32 KB
#define NSTAGE 3

__global__ __launch_bounds__(256, 2)
void gemm_split(const __nv_bfloat16* __restrict__ Ahi, const __nv_bfloat16* __restrict__ Alo,
                const __nv_bfloat16* __restrict__ Bhi, const __nv_bfloat16* __restrict__ Blo,
                float* __restrict__ Cf,
                __nv_bfloat16* __restrict__ Chi, __nv_bfloat16* __restrict__ Clo,
                const float* __restrict__ bias,
                int K, int N,
                long long sA, long long sB, long long sC)
{
    extern __shared__ __align__(128) char smem[];
    const uint32_t sb = smem_u32(smem);

    const int tid  = threadIdx.x;
    const int wid  = tid >> 5;
    const int lane = tid & 31;
    const int wm   = wid >> 2;       // 0..1 (64 rows each)
    const int wn   = wid & 3;        // 0..3 (32 cols each)

    const long long bz = blockIdx.z;
    const long long m0 = (long long)blockIdx.y * 128;
    const long long n0 = (long long)blockIdx.x * 128;

    const __nv_bfloat16* srcs[4] = {
        Ahi + bz * sA + m0 * K, Alo + bz * sA + m0 * K,
        Bhi + bz * sB + n0 * K, Blo + bz * sB + n0 * K };

    auto load_chunk = [&](int stage, int k0) {
        const uint32_t base = sb + stage * STAGE_B;
        #pragma unroll
        for (int t = 0; t < 4; ++t) {
            #pragma unroll
            for (int j = 0; j < 2; ++j) {
                int idx = tid * 2 + j;        // 0..511
                int row = idx >> 2;
                int ch  = idx & 3;
                cp16(tile_addr(base + t * TILE_B, row, ch),
                     srcs[t] + (long long)row * K + k0 + ch * 8);
            }
        }
        CP_COMMIT();
    };

    float acc[4][4][4];
    #pragma unroll
    for (int i = 0; i < 4; ++i)
        #pragma unroll
        for (int j = 0; j < 4; ++j)
            #pragma unroll
            for (int e = 0; e < 4; ++e) acc[i][j][e] = 0.f;

    const int NC = K >> 5;
    load_chunk(0, 0);
    load_chunk(1, BKC);

    const int lrow = lane & 15;
    const int lch  = lane >> 4;

    for (int c = 0; c < NC; ++c) {
        if (c + 1 < NC) CP_WAIT(1); else CP_WAIT(0);
        __syncthreads();
        if (c + 2 < NC) load_chunk((c + 2) % NSTAGE, (c + 2) * BKC);

        const uint32_t st  = sb + (c % NSTAGE) * STAGE_B;
        const uint32_t sAh = st;
        const uint32_t sAl = st + TILE_B;
        const uint32_t sBh = st + 2 * TILE_B;
        const uint32_t sBl = st + 3 * TILE_B;

        #pragma unroll
        for (int ks = 0; ks < 2; ++ks) {
            const int chunk = ks * 2 + lch;
            uint32_t ahi[4][4], alo[4][4];
            uint32_t bhi[4][2], blo[4][2];

            #pragma unroll
            for (int mi = 0; mi < 4; ++mi) {
                const int row = wm * 64 + mi * 16 + lrow;
                ldsm4(ahi[mi], tile_addr(sAh, row, chunk));
                ldsm4(alo[mi], tile_addr(sAl, row, chunk));
            }
            #pragma unroll
            for (int bi = 0; bi < 2; ++bi) {
                const int row = wn * 32 + bi * 16 + lrow;
                uint32_t t4[4];
                ldsm4(t4, tile_addr(sBh, row, chunk));
                bhi[bi*2][0]   = t4[0]; bhi[bi*2][1]   = t4[2];
                bhi[bi*2+1][0] = t4[1]; bhi[bi*2+1][1] = t4[3];
                ldsm4(t4, tile_addr(sBl, row, chunk));
                blo[bi*2][0]   = t4[0]; blo[bi*2][1]   = t4[2];
                blo[bi*2+1][0] = t4[1]; blo[bi*2+1][1] = t4[3];
            }

            #pragma unroll
            for (int mi = 0; mi < 4; ++mi)
                #pragma unroll
                for (int ni = 0; ni < 4; ++ni) {
                    mma16816(acc[mi][ni], ahi[mi], bhi[ni]);
                    mma16816(acc[mi][ni], ahi[mi], blo[ni]);
                    mma16816(acc[mi][ni], alo[mi], bhi[ni]);
                }
        }
        __syncthreads();
    }

    // ---- epilogue ----
    const int r1 = lane >> 2;
    const int c0 = (lane & 3) * 2;
    #pragma unroll
    for (int mi = 0; mi < 4; ++mi) {
        #pragma unroll
        for (int ni = 0; ni < 4; ++ni) {
            const long long gm = m0 + wm * 64 + mi * 16 + r1;
            const long long gn = n0 + wn * 32 + ni * 8 + c0;
            float v0 = acc[mi][ni][0], v1 = acc[mi][ni][1];
            float v2 = acc[mi][ni][2], v3 = acc[mi][ni][3];
            if (bias) {
                float b0 = bias[gn], b1 = bias[gn + 1];
                v0 += b0; v1 += b1; v2 += b0; v3 += b1;
            }
            if (Cf) {
                float* d0 = Cf + bz * sC + gm * N + gn;
                float* d1 = Cf + bz * sC + (gm + 8) * N + gn;
                d0[0] = v0; d0[1] = v1;
                d1[0] = v2; d1[1] = v3;
            } else {
                __nv_bfloat16 h0, h1, h2, h3, l0, l1, l2, l3;
                split1(v0, h0, l0); split1(v1, h1, l1);
                split1(v2, h2, l2); split1(v3, h3, l3);
                *(__nv_bfloat162*)(Chi + bz * sC + gm * N + gn)       = __nv_bfloat162(h0, h1);
                *(__nv_bfloat162*)(Clo + bz * sC + gm * N + gn)       = __nv_bfloat162(l0, l1);
                *(__nv_bfloat162*)(Chi + bz * sC + (gm + 8) * N + gn) = __nv_bfloat162(h2, h3);
                *(__nv_bfloat162*)(Clo + bz * sC + (gm + 8) * N + gn) = __nv_bfloat162(l2, l3);
            }
        }
    }
}

// ============================================================================
extern "C" void kernel_launch(void* const* d_in, const int* in_sizes, int n_in,
                              void* d_out, int out_size)
{
    const float* ix = (const float*)d_in[0];
    const float* io = (const float*)d_in[1];
    const float* W  = (const float*)d_in[2];
    const float* bb = (const float*)d_in[3];
    float* out = (float*)d_out;

    __nv_bfloat16 *ix_hi, *ix_lo, *io_hi, *io_lo, *ioT_hi, *ioT_lo;
    __nv_bfloat16 *ex_hi, *ex_lo, *eo_hi, *eo_lo, *w_hi, *w_lo, *p_hi, *p_lo;
    float* s;
    cudaGetSymbolAddress((void**)&ix_hi, g_ix_hi);
    cudaGetSymbolAddress((void**)&ix_lo, g_ix_lo);
    cudaGetSymbolAddress((void**)&io_hi, g_io_hi);
    cudaGetSymbolAddress((void**)&io_lo, g_io_lo);
    cudaGetSymbolAddress((void**)&ioT_hi, g_ioT_hi);
    cudaGetSymbolAddress((void**)&ioT_lo, g_ioT_lo);
    cudaGetSymbolAddress((void**)&ex_hi, g_ex_hi);
    cudaGetSymbolAddress((void**)&ex_lo, g_ex_lo);
    cudaGetSymbolAddress((void**)&eo_hi, g_eo_hi);
    cudaGetSymbolAddress((void**)&eo_lo, g_eo_lo);
    cudaGetSymbolAddress((void**)&w_hi, g_w_hi);
    cudaGetSymbolAddress((void**)&w_lo, g_w_lo);
    cudaGetSymbolAddress((void**)&p_hi, g_p_hi);
    cudaGetSymbolAddress((void**)&p_lo, g_p_lo);
    cudaGetSymbolAddress((void**)&s, g_s);

    static bool attr_set = false;
    const int smem_bytes = NSTAGE * STAGE_B;  // 96 KB
    if (!attr_set) {
        cudaFuncSetAttribute(gemm_split,
                             cudaFuncAttributeMaxDynamicSharedMemorySize, smem_bytes);
        attr_set = true;
    }

    // 1) splits
    split_f32<<<(unsigned)(MELEMS / 4 / 256), 256>>>(ix, ix_hi, ix_lo, MELEMS);
    split_f32<<<(unsigned)(MELEMS / 4 / 256), 256>>>(io, io_hi, io_lo, MELEMS);
    split_f32<<<(DIM * DIM) / 4 / 256, 256>>>(W, w_hi, w_lo, (size_t)DIM * DIM);
    transpose_split<<<dim3(LSEQ / 32, DIM / 32, BATCH), dim3(32, 8)>>>(io, ioT_hi, ioT_lo);

    // 2) projections: E = X @ W^T + b -> bf16 split (M=16384, N=1024, K=1024)
    {
        dim3 g(DIM / 128, (BATCH * LSEQ) / 128, 1);
        gemm_split<<<g, 256, smem_bytes>>>(ix_hi, ix_lo, w_hi, w_lo,
                                           nullptr, ex_hi, ex_lo, bb,
                                           DIM, DIM, 0, 0, 0);
        gemm_split<<<g, 256, smem_bytes>>>(io_hi, io_lo, w_hi, w_lo,
                                           nullptr, eo_hi, eo_lo, bb,
                                           DIM, DIM, 0, 0, 0);
    }

    // 3) scores: S[b] = Ex[b] @ Eo[b]^T -> fp32 (M=N=2048, K=1024)
    {
        dim3 g(LSEQ / 128, LSEQ / 128, BATCH);
        gemm_split<<<g, 256, smem_bytes>>>(ex_hi, ex_lo, eo_hi, eo_lo,
                                           s, nullptr, nullptr, nullptr,
                                           DIM, LSEQ,
                                           (long long)LSEQ * DIM,
                                           (long long)LSEQ * DIM,
                                           (long long)LSEQ * LSEQ);
    }

    // 4) softmax -> P bf16 split
    softmax_split<<<BATCH * LSEQ, 256>>>(s, p_hi, p_lo, LSEQ);

    // 5) out[b] = P[b] @ ioT[b]^T -> fp32 d_out (M=2048, N=1024, K=2048)
    {
        dim3 g(DIM / 128, LSEQ / 128, BATCH);
        gemm_split<<<g, 256, smem_bytes>>>(p_hi, p_lo, ioT_hi, ioT_lo,
                                           out, nullptr, nullptr, nullptr,
                                           LSEQ, DIM,
                                           (long long)LSEQ * LSEQ,
                                           (long long)DIM * LSEQ,
                                           (long long)LSEQ * DIM);
    }
}

// round 6
// speedup vs baseline: 1.4185x; 1.1137x over previous
#include <cuda_runtime.h>
#include <cuda_bf16.h>
#include <cstdint>
#include <math.h>

// ============================================================================
// Aligner: out = softmax((ix@W^T+b) @ (io@W^T+b)^T) @ io
// B=8, L=2048, D=1024, fp32 in/out.
// Round 6: algebraic restructure. With A=W^T, M=A@A^T=W^T@W (symmetric):
//   align = (ix@M)@io^T + q[l] + r[m] + |b|^2
// q[l] and |b|^2 are softmax-invariant (dropped); r[m]=io[m]@(W^T b) is added
// in the softmax kernel. Removes the eo projection GEMM (103 GF of 618).
// All GEMMs remain 3-pass split-precision HMMA (hi*hi + hi*lo + lo*hi).
// ============================================================================

#define BATCH 8
#define LSEQ  2048
#define DIM   1024
#define MELEMS ((size_t)BATCH * LSEQ * DIM)
#define SELEMS ((size_t)BATCH * LSEQ * LSEQ)

// ---- scratch (__device__ globals per allocation rules) ----
__device__ __nv_bfloat16 g_ix_hi[MELEMS],  g_ix_lo[MELEMS];
__device__ __nv_bfloat16 g_io_hi[MELEMS],  g_io_lo[MELEMS];
__device__ __nv_bfloat16 g_ioT_hi[MELEMS], g_ioT_lo[MELEMS];
__device__ __nv_bfloat16 g_t_hi[MELEMS],   g_t_lo[MELEMS];
__device__ __nv_bfloat16 g_wt_hi[DIM * DIM], g_wt_lo[DIM * DIM];
__device__ __nv_bfloat16 g_m_hi[DIM * DIM],  g_m_lo[DIM * DIM];
__device__ float         g_s[SELEMS];
__device__ __nv_bfloat16 g_p_hi[SELEMS],   g_p_lo[SELEMS];
__device__ float         g_p_vec[DIM];                 // p = W^T b
__device__ float         g_r[(size_t)BATCH * LSEQ];    // r[b,m] = io[b,m]·p

// ============================================================================
// PTX helpers (portable only)
// ============================================================================
__device__ __forceinline__ uint32_t smem_u32(const void* p) {
    uint32_t a;
    asm("{ .reg .u64 t; cvta.to.shared.u64 t, %1; cvt.u32.u64 %0, t; }"
        : "=r"(a) : "l"(p));
    return a;
}

#define CP_COMMIT() asm volatile("cp.async.commit_group;" ::: "memory")
#define CP_WAIT(N)  asm volatile("cp.async.wait_group %0;" :: "n"(N) : "memory")

__device__ __forceinline__ void cp16(uint32_t dst, const void* src) {
    asm volatile("cp.async.cg.shared.global [%0], [%1], 16;" :: "r"(dst), "l"(src));
}

__device__ __forceinline__ void ldsm4(uint32_t* r, uint32_t addr) {
    asm volatile("ldmatrix.sync.aligned.m8n8.x4.shared.b16 {%0,%1,%2,%3}, [%4];"
                 : "=r"(r[0]), "=r"(r[1]), "=r"(r[2]), "=r"(r[3]) : "r"(addr));
}

__device__ __forceinline__ void mma16816(float* d, const uint32_t* a,
                                         const uint32_t* b) {
    asm volatile(
        "mma.sync.aligned.m16n8k16.row.col.f32.bf16.bf16.f32 "
        "{%0,%1,%2,%3}, {%4,%5,%6,%7}, {%8,%9}, {%0,%1,%2,%3};"
        : "+f"(d[0]), "+f"(d[1]), "+f"(d[2]), "+f"(d[3])
        : "r"(a[0]), "r"(a[1]), "r"(a[2]), "r"(a[3]), "r"(b[0]), "r"(b[1]));
}

// tile layout: [rows][64 bytes], 16B chunks swizzled: chunk ^ ((row>>1)&3)
__device__ __forceinline__ uint32_t tile_addr(uint32_t base, int row, int chunk) {
    return base + row * 64 + ((chunk ^ ((row >> 1) & 3)) << 4);
}

// ============================================================================
// Helper kernels
// ============================================================================
__device__ __forceinline__ void split1(float v, __nv_bfloat16& h, __nv_bfloat16& l) {
    h = __float2bfloat16(v);
    l = __float2bfloat16(v - __bfloat162float(h));
}

__global__ void split_f32(const float* __restrict__ s,
                          __nv_bfloat16* __restrict__ hi,
                          __nv_bfloat16* __restrict__ lo, size_t n) {
    size_t i = ((size_t)blockIdx.x * blockDim.x + threadIdx.x) * 4;
    if (i >= n) return;
    float4 v = *(const float4*)(s + i);
    __nv_bfloat16 h0, h1, h2, h3, l0, l1, l2, l3;
    split1(v.x, h0, l0); split1(v.y, h1, l1);
    split1(v.z, h2, l2); split1(v.w, h3, l3);
    *(__nv_bfloat162*)(hi + i)     = __nv_bfloat162(h0, h1);
    *(__nv_bfloat162*)(hi + i + 2) = __nv_bfloat162(h2, h3);
    *(__nv_bfloat162*)(lo + i)     = __nv_bfloat162(l0, l1);
    *(__nv_bfloat162*)(lo + i + 2) = __nv_bfloat162(l2, l3);
}

// per-batch transpose [rows, cols] -> [cols, rows] with bf16 split outputs
__global__ void transpose_split(const float* __restrict__ src,
                                __nv_bfloat16* __restrict__ hiT,
                                __nv_bfloat16* __restrict__ loT,
                                int rows, int cols) {
    __shared__ float t[32][33];
    int b = blockIdx.z;
    int r0 = blockIdx.x * 32, c0 = blockIdx.y * 32;
    const float* s = src + (size_t)b * rows * cols;
    #pragma unroll
    for (int i = 0; i < 32; i += 8)
        t[threadIdx.y + i][threadIdx.x] =
            s[(size_t)(r0 + threadIdx.y + i) * cols + c0 + threadIdx.x];
    __syncthreads();
    size_t ob = (size_t)b * rows * cols;
    #pragma unroll
    for (int i = 0; i < 32; i += 8) {
        float v = t[threadIdx.x][threadIdx.y + i];
        __nv_bfloat16 h, l;
        split1(v, h, l);
        size_t o = ob + (size_t)(c0 + threadIdx.y + i) * rows + r0 + threadIdx.x;
        hiT[o] = h;
        loT[o] = l;
    }
}

// p[i] = sum_k b[k] * W[k,i]   (grid 8 x 128 threads)
__global__ void compute_p(const float* __restrict__ W,
                          const float* __restrict__ b,
                          float* __restrict__ p) {
    int i = blockIdx.x * 128 + threadIdx.x;
    float acc = 0.f;
    for (int k = 0; k < DIM; ++k)
        acc += b[k] * W[(size_t)k * DIM + i];
    p[i] = acc;
}

// r[row] = io[row,:]·p   (one warp per row)
__global__ void compute_r(const float* __restrict__ io,
                          const float* __restrict__ p,
                          float* __restrict__ r) {
    int row  = blockIdx.x * 8 + (threadIdx.x >> 5);
    int lane = threadIdx.x & 31;
    const float* src = io + (size_t)row * DIM;
    float acc = 0.f;
    for (int d = lane * 4; d < DIM; d += 128) {
        float4 v  = *(const float4*)(src + d);
        float4 pv = *(const float4*)(p + d);
        acc += v.x * pv.x + v.y * pv.y + v.z * pv.z + v.w * pv.w;
    }
    #pragma unroll
    for (int o = 16; o; o >>= 1)
        acc += __shfl_xor_sync(0xFFFFFFFFu, acc, o);
    if (lane == 0) r[row] = acc;
}

// row softmax of (S[row,:] + r[b,:]); writes bf16 hi/lo probability split
__global__ void softmax_split(float* __restrict__ S,
                              const float* __restrict__ r,
                              __nv_bfloat16* __restrict__ phi,
                              __nv_bfloat16* __restrict__ plo, int cols) {
    float* row = S + (size_t)blockIdx.x * cols;
    const float* rr = r + (size_t)(blockIdx.x / LSEQ) * LSEQ;
    __nv_bfloat16* hr = phi + (size_t)blockIdx.x * cols;
    __nv_bfloat16* lr = plo + (size_t)blockIdx.x * cols;
    const int tid = threadIdx.x;

    float lmax = -3.0e38f;
    for (int i = tid * 4; i < cols; i += 1024) {
        float4 v = *(const float4*)(row + i);
        float4 a = *(const float4*)(rr + i);
        v.x += a.x; v.y += a.y; v.z += a.z; v.w += a.w;
        lmax = fmaxf(lmax, fmaxf(fmaxf(v.x, v.y), fmaxf(v.z, v.w)));
    }
    #pragma unroll
    for (int o = 16; o; o >>= 1)
        lmax = fmaxf(lmax, __shfl_xor_sync(0xFFFFFFFFu, lmax, o));
    __shared__ float sm[8], ss[8];
    if ((tid & 31) == 0) sm[tid >> 5] = lmax;
    __syncthreads();
    float rmax = fmaxf(fmaxf(fmaxf(sm[0], sm[1]), fmaxf(sm[2], sm[3])),
                       fmaxf(fmaxf(sm[4], sm[5]), fmaxf(sm[6], sm[7])));

    float lsum = 0.f;
    for (int i = tid * 4; i < cols; i += 1024) {
        float4 v = *(const float4*)(row + i);
        float4 a = *(const float4*)(rr + i);
        v.x = expf(v.x + a.x - rmax); v.y = expf(v.y + a.y - rmax);
        v.z = expf(v.z + a.z - rmax); v.w = expf(v.w + a.w - rmax);
        *(float4*)(row + i) = v;
        lsum += v.x + v.y + v.z + v.w;
    }
    #pragma unroll
    for (int o = 16; o; o >>= 1)
        lsum += __shfl_xor_sync(0xFFFFFFFFu, lsum, o);
    if ((tid & 31) == 0) ss[tid >> 5] = lsum;
    __syncthreads();
    float inv = 1.f / (ss[0]+ss[1]+ss[2]+ss[3]+ss[4]+ss[5]+ss[6]+ss[7]);

    for (int i = tid * 4; i < cols; i += 1024) {
        float4 v = *(const float4*)(row + i);
        v.x *= inv; v.y *= inv; v.z *= inv; v.w *= inv;
        __nv_bfloat16 h0,h1,h2,h3,l0,l1,l2,l3;
        split1(v.x,h0,l0); split1(v.y,h1,l1); split1(v.z,h2,l2); split1(v.w,h3,l3);
        *(__nv_bfloat162*)(hr + i)     = __nv_bfloat162(h0, h1);
        *(__nv_bfloat162*)(hr + i + 2) = __nv_bfloat162(h2, h3);
        *(__nv_bfloat162*)(lr + i)     = __nv_bfloat162(l0, l1);
        *(__nv_bfloat162*)(lr + i + 2) = __nv_bfloat162(l2, l3);
    }
}

// ============================================================================
// Split-precision HMMA GEMM, CTA 128x128, warp tile 64x32, K-chunk 32.
// 3 smem stages (prefetch depth 2), 2 CTAs/SM.  (R5 config — known good.)
// ============================================================================
#define BKC 32
#define TILE_B 8192
#define STAGE_B (4 * TILE_B)     // 32 KB
#define NSTAGE 3

__global__ __launch_bounds__(256, 2)
void gemm_split(const __nv_bfloat16* __restrict__ Ahi, const __nv_bfloat16* __restrict__ Alo,
                const __nv_bfloat16* __restrict__ Bhi, const __nv_bfloat16* __restrict__ Blo,
                float* __restrict__ Cf,
                __nv_bfloat16* __restrict__ Chi, __nv_bfloat16* __restrict__ Clo,
                int K, int N,
                long long sA, long long sB, long long sC)
{
    extern __shared__ __align__(128) char smem[];
    const uint32_t sb = smem_u32(smem);

    const int tid  = threadIdx.x;
    const int wid  = tid >> 5;
    const int lane = tid & 31;
    const int wm   = wid >> 2;
    const int wn   = wid & 3;

    const long long bz = blockIdx.z;
    const long long m0 = (long long)blockIdx.y * 128;
    const long long n0 = (long long)blockIdx.x * 128;

    const __nv_bfloat16* srcs[4] = {
        Ahi + bz * sA + m0 * K, Alo + bz * sA + m0 * K,
        Bhi + bz * sB + n0 * K, Blo + bz * sB + n0 * K };

    auto load_chunk = [&](int stage, int k0) {
        const uint32_t base = sb + stage * STAGE_B;
        #pragma unroll
        for (int t = 0; t < 4; ++t) {
            #pragma unroll
            for (int j = 0; j < 2; ++j) {
                int idx = tid * 2 + j;
                int row = idx >> 2;
                int ch  = idx & 3;
                cp16(tile_addr(base + t * TILE_B, row, ch),
                     srcs[t] + (long long)row * K + k0 + ch * 8);
            }
        }
        CP_COMMIT();
    };

    float acc[4][4][4];
    #pragma unroll
    for (int i = 0; i < 4; ++i)
        #pragma unroll
        for (int j = 0; j < 4; ++j)
            #pragma unroll
            for (int e = 0; e < 4; ++e) acc[i][j][e] = 0.f;

    const int NC = K >> 5;
    load_chunk(0, 0);
    load_chunk(1, BKC);

    const int lrow = lane & 15;
    const int lch  = lane >> 4;

    for (int c = 0; c < NC; ++c) {
        if (c + 1 < NC) CP_WAIT(1); else CP_WAIT(0);
        __syncthreads();
        if (c + 2 < NC) load_chunk((c + 2) % NSTAGE, (c + 2) * BKC);

        const uint32_t st  = sb + (c % NSTAGE) * STAGE_B;
        const uint32_t sAh = st;
        const uint32_t sAl = st + TILE_B;
        const uint32_t sBh = st + 2 * TILE_B;
        const uint32_t sBl = st + 3 * TILE_B;

        #pragma unroll
        for (int ks = 0; ks < 2; ++ks) {
            const int chunk = ks * 2 + lch;
            uint32_t ahi[4][4], alo[4][4];
            uint32_t bhi[4][2], blo[4][2];

            #pragma unroll
            for (int mi = 0; mi < 4; ++mi) {
                const int row = wm * 64 + mi * 16 + lrow;
                ldsm4(ahi[mi], tile_addr(sAh, row, chunk));
                ldsm4(alo[mi], tile_addr(sAl, row, chunk));
            }
            #pragma unroll
            for (int bi = 0; bi < 2; ++bi) {
                const int row = wn * 32 + bi * 16 + lrow;
                uint32_t t4[4];
                ldsm4(t4, tile_addr(sBh, row, chunk));
                bhi[bi*2][0]   = t4[0]; bhi[bi*2][1]   = t4[2];
                bhi[bi*2+1][0] = t4[1]; bhi[bi*2+1][1] = t4[3];
                ldsm4(t4, tile_addr(sBl, row, chunk));
                blo[bi*2][0]   = t4[0]; blo[bi*2][1]   = t4[2];
                blo[bi*2+1][0] = t4[1]; blo[bi*2+1][1] = t4[3];
            }

            #pragma unroll
            for (int mi = 0; mi < 4; ++mi)
                #pragma unroll
                for (int ni = 0; ni < 4; ++ni) {
                    mma16816(acc[mi][ni], ahi[mi], bhi[ni]);
                    mma16816(acc[mi][ni], ahi[mi], blo[ni]);
                    mma16816(acc[mi][ni], alo[mi], bhi[ni]);
                }
        }
        __syncthreads();
    }

    // ---- epilogue ----
    const int r1 = lane >> 2;
    const int c0 = (lane & 3) * 2;
    #pragma unroll
    for (int mi = 0; mi < 4; ++mi) {
        #pragma unroll
        for (int ni = 0; ni < 4; ++ni) {
            const long long gm = m0 + wm * 64 + mi * 16 + r1;
            const long long gn = n0 + wn * 32 + ni * 8 + c0;
            float v0 = acc[mi][ni][0], v1 = acc[mi][ni][1];
            float v2 = acc[mi][ni][2], v3 = acc[mi][ni][3];
            if (Cf) {
                float* d0 = Cf + bz * sC + gm * N + gn;
                float* d1 = Cf + bz * sC + (gm + 8) * N + gn;
                d0[0] = v0; d0[1] = v1;
                d1[0] = v2; d1[1] = v3;
            } else {
                __nv_bfloat16 h0, h1, h2, h3, l0, l1, l2, l3;
                split1(v0, h0, l0); split1(v1, h1, l1);
                split1(v2, h2, l2); split1(v3, h3, l3);
                *(__nv_bfloat162*)(Chi + bz * sC + gm * N + gn)       = __nv_bfloat162(h0, h1);
                *(__nv_bfloat162*)(Clo + bz * sC + gm * N + gn)       = __nv_bfloat162(l0, l1);
                *(__nv_bfloat162*)(Chi + bz * sC + (gm + 8) * N + gn) = __nv_bfloat162(h2, h3);
                *(__nv_bfloat162*)(Clo + bz * sC + (gm + 8) * N + gn) = __nv_bfloat162(l2, l3);
            }
        }
    }
}

// ============================================================================
extern "C" void kernel_launch(void* const* d_in, const int* in_sizes, int n_in,
                              void* d_out, int out_size)
{
    const float* ix = (const float*)d_in[0];
    const float* io = (const float*)d_in[1];
    const float* W  = (const float*)d_in[2];
    const float* bb = (const float*)d_in[3];
    float* out = (float*)d_out;

    __nv_bfloat16 *ix_hi, *ix_lo, *io_hi, *io_lo, *ioT_hi, *ioT_lo;
    __nv_bfloat16 *t_hi, *t_lo, *wt_hi, *wt_lo, *m_hi, *m_lo, *p_hi, *p_lo;
    float *s, *pv, *rv;
    cudaGetSymbolAddress((void**)&ix_hi, g_ix_hi);
    cudaGetSymbolAddress((void**)&ix_lo, g_ix_lo);
    cudaGetSymbolAddress((void**)&io_hi, g_io_hi);
    cudaGetSymbolAddress((void**)&io_lo, g_io_lo);
    cudaGetSymbolAddress((void**)&ioT_hi, g_ioT_hi);
    cudaGetSymbolAddress((void**)&ioT_lo, g_ioT_lo);
    cudaGetSymbolAddress((void**)&t_hi, g_t_hi);
    cudaGetSymbolAddress((void**)&t_lo, g_t_lo);
    cudaGetSymbolAddress((void**)&wt_hi, g_wt_hi);
    cudaGetSymbolAddress((void**)&wt_lo, g_wt_lo);
    cudaGetSymbolAddress((void**)&m_hi, g_m_hi);
    cudaGetSymbolAddress((void**)&m_lo, g_m_lo);
    cudaGetSymbolAddress((void**)&p_hi, g_p_hi);
    cudaGetSymbolAddress((void**)&p_lo, g_p_lo);
    cudaGetSymbolAddress((void**)&s, g_s);
    cudaGetSymbolAddress((void**)&pv, g_p_vec);
    cudaGetSymbolAddress((void**)&rv, g_r);

    static bool attr_set = false;
    const int smem_bytes = NSTAGE * STAGE_B;  // 96 KB
    if (!attr_set) {
        cudaFuncSetAttribute(gemm_split,
                             cudaFuncAttributeMaxDynamicSharedMemorySize, smem_bytes);
        attr_set = true;
    }

    // 1) splits + transposes + bias vectors
    split_f32<<<(unsigned)(MELEMS / 4 / 256), 256>>>(ix, ix_hi, ix_lo, MELEMS);
    split_f32<<<(unsigned)(MELEMS / 4 / 256), 256>>>(io, io_hi, io_lo, MELEMS);
    transpose_split<<<dim3(LSEQ / 32, DIM / 32, BATCH), dim3(32, 8)>>>(
        io, ioT_hi, ioT_lo, LSEQ, DIM);
    transpose_split<<<dim3(DIM / 32, DIM / 32, 1), dim3(32, 8)>>>(
        W, wt_hi, wt_lo, DIM, DIM);                 // WT[i,k] = W[k,i]
    compute_p<<<DIM / 128, 128>>>(W, bb, pv);       // p = W^T b
    compute_r<<<(BATCH * LSEQ) / 8, 256>>>(io, pv, rv);

    // 2) M = WT @ WT^T = W^T W (symmetric) -> bf16 split (1024x1024, K=1024)
    {
        dim3 g(DIM / 128, DIM / 128, 1);
        gemm_split<<<g, 256, smem_bytes>>>(wt_hi, wt_lo, wt_hi, wt_lo,
                                           nullptr, m_hi, m_lo,
                                           DIM, DIM, 0, 0, 0);
    }

    // 3) t = ix @ M^T (= ix @ M, symmetric) -> bf16 split (16384x1024, K=1024)
    {
        dim3 g(DIM / 128, (BATCH * LSEQ) / 128, 1);
        gemm_split<<<g, 256, smem_bytes>>>(ix_hi, ix_lo, m_hi, m_lo,
                                           nullptr, t_hi, t_lo,
                                           DIM, DIM, 0, 0, 0);
    }

    // 4) scores: S[b] = t[b] @ io[b]^T -> fp32 (2048x2048, K=1024)
    {
        dim3 g(LSEQ / 128, LSEQ / 128, BATCH);
        gemm_split<<<g, 256, smem_bytes>>>(t_hi, t_lo, io_hi, io_lo,
                                           s, nullptr, nullptr,
                                           DIM, LSEQ,
                                           (long long)LSEQ * DIM,
                                           (long long)LSEQ * DIM,
                                           (long long)LSEQ * LSEQ);
    }

    // 5) softmax(S + r) -> P bf16 split
    softmax_split<<<BATCH * LSEQ, 256>>>(s, rv, p_hi, p_lo, LSEQ);

    // 6) out[b] = P[b] @ ioT[b]^T -> fp32 d_out (2048x1024, K=2048)
    {
        dim3 g(DIM / 128, LSEQ / 128, BATCH);
        gemm_split<<<g, 256, smem_bytes>>>(p_hi, p_lo, ioT_hi, ioT_lo,
                                           out, nullptr, nullptr,
                                           LSEQ, DIM,
                                           (long long)LSEQ * LSEQ,
                                           (long long)DIM * LSEQ,
                                           (long long)LSEQ * DIM);
    }
}

// round 7
// speedup vs baseline: 1.5778x; 1.1123x over previous
#include <cuda_runtime.h>
#include <cuda_fp16.h>
#include <cstdint>
#include <math.h>

// ============================================================================
// Aligner: out = softmax((ix@W^T+b) @ (io@W^T+b)^T) @ io
// B=8, L=2048, D=1024, fp32 in/out.
// Round 7: fp16 split precision (10 mantissa bits vs bf16's 8).
//   M = W^T W;  t = ix@M;  S = t@io^T (+ r[m] in softmax);  out = P@io.
//   M/t/S GEMMs: 3-pass (hi*hi + hi*lo + lo*hi), error ~2^-22.
//   out GEMM: 2-pass (Ph*ioh + Pl*ioh), io at fp16-hi only (err ~2.8e-4).
// ============================================================================

#define BATCH 8
#define LSEQ  2048
#define DIM   1024
#define MELEMS ((size_t)BATCH * LSEQ * DIM)
#define SELEMS ((size_t)BATCH * LSEQ * LSEQ)

// ---- scratch (__device__ globals per allocation rules) ----
__device__ __half g_ix_hi[MELEMS],  g_ix_lo[MELEMS];
__device__ __half g_io_hi[MELEMS],  g_io_lo[MELEMS];
__device__ __half g_ioT_hi[MELEMS];
__device__ __half g_t_hi[MELEMS],   g_t_lo[MELEMS];
__device__ __half g_wt_hi[DIM * DIM], g_wt_lo[DIM * DIM];
__device__ __half g_m_hi[DIM * DIM],  g_m_lo[DIM * DIM];
__device__ float  g_s[SELEMS];
__device__ __half g_p_hi[SELEMS],   g_p_lo[SELEMS];
__device__ float  g_p_vec[DIM];                 // p = W^T b
__device__ float  g_r[(size_t)BATCH * LSEQ];    // r[b,m] = io[b,m]·p

// ============================================================================
// PTX helpers (portable only)
// ============================================================================
__device__ __forceinline__ uint32_t smem_u32(const void* p) {
    uint32_t a;
    asm("{ .reg .u64 t; cvta.to.shared.u64 t, %1; cvt.u32.u64 %0, t; }"
        : "=r"(a) : "l"(p));
    return a;
}

#define CP_COMMIT() asm volatile("cp.async.commit_group;" ::: "memory")
#define CP_WAIT(N)  asm volatile("cp.async.wait_group %0;" :: "n"(N) : "memory")

__device__ __forceinline__ void cp16(uint32_t dst, const void* src) {
    asm volatile("cp.async.cg.shared.global [%0], [%1], 16;" :: "r"(dst), "l"(src));
}

__device__ __forceinline__ void ldsm4(uint32_t* r, uint32_t addr) {
    asm volatile("ldmatrix.sync.aligned.m8n8.x4.shared.b16 {%0,%1,%2,%3}, [%4];"
                 : "=r"(r[0]), "=r"(r[1]), "=r"(r[2]), "=r"(r[3]) : "r"(addr));
}

__device__ __forceinline__ void mma16816(float* d, const uint32_t* a,
                                         const uint32_t* b) {
    asm volatile(
        "mma.sync.aligned.m16n8k16.row.col.f32.f16.f16.f32 "
        "{%0,%1,%2,%3}, {%4,%5,%6,%7}, {%8,%9}, {%0,%1,%2,%3};"
        : "+f"(d[0]), "+f"(d[1]), "+f"(d[2]), "+f"(d[3])
        : "r"(a[0]), "r"(a[1]), "r"(a[2]), "r"(a[3]), "r"(b[0]), "r"(b[1]));
}

// tile layout: [rows][64 bytes], 16B chunks swizzled: chunk ^ ((row>>1)&3)
__device__ __forceinline__ uint32_t tile_addr(uint32_t base, int row, int chunk) {
    return base + row * 64 + ((chunk ^ ((row >> 1) & 3)) << 4);
}

// ============================================================================
// Helper kernels
// ============================================================================
__device__ __forceinline__ void split1(float v, __half& h, __half& l) {
    h = __float2half(v);
    l = __float2half(v - __half2float(h));
}

__global__ void split_f32(const float* __restrict__ s,
                          __half* __restrict__ hi,
                          __half* __restrict__ lo, size_t n) {
    size_t i = ((size_t)blockIdx.x * blockDim.x + threadIdx.x) * 4;
    if (i >= n) return;
    float4 v = *(const float4*)(s + i);
    __half h0, h1, h2, h3, l0, l1, l2, l3;
    split1(v.x, h0, l0); split1(v.y, h1, l1);
    split1(v.z, h2, l2); split1(v.w, h3, l3);
    *(__half2*)(hi + i)     = __halves2half2(h0, h1);
    *(__half2*)(hi + i + 2) = __halves2half2(h2, h3);
    *(__half2*)(lo + i)     = __halves2half2(l0, l1);
    *(__half2*)(lo + i + 2) = __halves2half2(l2, l3);
}

// per-batch transpose [rows, cols] -> [cols, rows]; lo output optional
__global__ void transpose_split(const float* __restrict__ src,
                                __half* __restrict__ hiT,
                                __half* __restrict__ loT,
                                int rows, int cols) {
    __shared__ float t[32][33];
    int b = blockIdx.z;
    int r0 = blockIdx.x * 32, c0 = blockIdx.y * 32;
    const float* s = src + (size_t)b * rows * cols;
    #pragma unroll
    for (int i = 0; i < 32; i += 8)
        t[threadIdx.y + i][threadIdx.x] =
            s[(size_t)(r0 + threadIdx.y + i) * cols + c0 + threadIdx.x];
    __syncthreads();
    size_t ob = (size_t)b * rows * cols;
    #pragma unroll
    for (int i = 0; i < 32; i += 8) {
        float v = t[threadIdx.x][threadIdx.y + i];
        __half h, l;
        split1(v, h, l);
        size_t o = ob + (size_t)(c0 + threadIdx.y + i) * rows + r0 + threadIdx.x;
        hiT[o] = h;
        if (loT) loT[o] = l;
    }
}

// p[i] = sum_k b[k] * W[k,i]
__global__ void compute_p(const float* __restrict__ W,
                          const float* __restrict__ b,
                          float* __restrict__ p) {
    int i = blockIdx.x * 128 + threadIdx.x;
    float acc = 0.f;
    for (int k = 0; k < DIM; ++k)
        acc += b[k] * W[(size_t)k * DIM + i];
    p[i] = acc;
}

// r[row] = io[row,:]·p   (one warp per row)
__global__ void compute_r(const float* __restrict__ io,
                          const float* __restrict__ p,
                          float* __restrict__ r) {
    int row  = blockIdx.x * 8 + (threadIdx.x >> 5);
    int lane = threadIdx.x & 31;
    const float* src = io + (size_t)row * DIM;
    float acc = 0.f;
    for (int d = lane * 4; d < DIM; d += 128) {
        float4 v  = *(const float4*)(src + d);
        float4 pv = *(const float4*)(p + d);
        acc += v.x * pv.x + v.y * pv.y + v.z * pv.z + v.w * pv.w;
    }
    #pragma unroll
    for (int o = 16; o; o >>= 1)
        acc += __shfl_xor_sync(0xFFFFFFFFu, acc, o);
    if (lane == 0) r[row] = acc;
}

// row softmax of (S[row,:] + r[b,:]); writes fp16 hi/lo probability split
__global__ void softmax_split(float* __restrict__ S,
                              const float* __restrict__ r,
                              __half* __restrict__ phi,
                              __half* __restrict__ plo, int cols) {
    float* row = S + (size_t)blockIdx.x * cols;
    const float* rr = r + (size_t)(blockIdx.x / LSEQ) * LSEQ;
    __half* hr = phi + (size_t)blockIdx.x * cols;
    __half* lr = plo + (size_t)blockIdx.x * cols;
    const int tid = threadIdx.x;

    float lmax = -3.0e38f;
    for (int i = tid * 4; i < cols; i += 1024) {
        float4 v = *(const float4*)(row + i);
        float4 a = *(const float4*)(rr + i);
        v.x += a.x; v.y += a.y; v.z += a.z; v.w += a.w;
        lmax = fmaxf(lmax, fmaxf(fmaxf(v.x, v.y), fmaxf(v.z, v.w)));
    }
    #pragma unroll
    for (int o = 16; o; o >>= 1)
        lmax = fmaxf(lmax, __shfl_xor_sync(0xFFFFFFFFu, lmax, o));
    __shared__ float sm[8], ss[8];
    if ((tid & 31) == 0) sm[tid >> 5] = lmax;
    __syncthreads();
    float rmax = fmaxf(fmaxf(fmaxf(sm[0], sm[1]), fmaxf(sm[2], sm[3])),
                       fmaxf(fmaxf(sm[4], sm[5]), fmaxf(sm[6], sm[7])));

    float lsum = 0.f;
    for (int i = tid * 4; i < cols; i += 1024) {
        float4 v = *(const float4*)(row + i);
        float4 a = *(const float4*)(rr + i);
        v.x = expf(v.x + a.x - rmax); v.y = expf(v.y + a.y - rmax);
        v.z = expf(v.z + a.z - rmax); v.w = expf(v.w + a.w - rmax);
        *(float4*)(row + i) = v;
        lsum += v.x + v.y + v.z + v.w;
    }
    #pragma unroll
    for (int o = 16; o; o >>= 1)
        lsum += __shfl_xor_sync(0xFFFFFFFFu, lsum, o);
    if ((tid & 31) == 0) ss[tid >> 5] = lsum;
    __syncthreads();
    float inv = 1.f / (ss[0]+ss[1]+ss[2]+ss[3]+ss[4]+ss[5]+ss[6]+ss[7]);

    for (int i = tid * 4; i < cols; i += 1024) {
        float4 v = *(const float4*)(row + i);
        v.x *= inv; v.y *= inv; v.z *= inv; v.w *= inv;
        __half h0,h1,h2,h3,l0,l1,l2,l3;
        split1(v.x,h0,l0); split1(v.y,h1,l1); split1(v.z,h2,l2); split1(v.w,h3,l3);
        *(__half2*)(hr + i)     = __halves2half2(h0, h1);
        *(__half2*)(hr + i + 2) = __halves2half2(h2, h3);
        *(__half2*)(lr + i)     = __halves2half2(l0, l1);
        *(__half2*)(lr + i + 2) = __halves2half2(l2, l3);
    }
}

// ============================================================================
// Split-precision HMMA GEMM, CTA 128x128, warp tile 64x32, K-chunk 32.
// 3 smem stages (prefetch depth 2), 2 CTAs/SM.
// NPASS=3: C = Ah*Bh + Ah*Bl + Al*Bh (tiles: Ah, Al, Bh, Bl)
// NPASS=2: C = Ah*Bh + Al*Bh          (tiles: Ah, Al, Bh) — A full, B hi-only
// ============================================================================
#define BKC 32
#define TILE_B 8192

template<int NPASS>
__global__ __launch_bounds__(256, 2)
void gemm_split(const __half* __restrict__ Ahi, const __half* __restrict__ Alo,
                const __half* __restrict__ Bhi, const __half* __restrict__ Blo,
                float* __restrict__ Cf,
                __half* __restrict__ Chi, __half* __restrict__ Clo,
                int K, int N,
                long long sA, long long sB, long long sC)
{
    constexpr int NT = (NPASS == 3) ? 4 : 3;
    constexpr int STAGE_B = NT * TILE_B;
    constexpr int NSTAGE = 3;

    extern __shared__ __align__(128) char smem[];
    const uint32_t sb = smem_u32(smem);

    const int tid  = threadIdx.x;
    const int wid  = tid >> 5;
    const int lane = tid & 31;
    const int wm   = wid >> 2;
    const int wn   = wid & 3;

    const long long bz = blockIdx.z;
    const long long m0 = (long long)blockIdx.y * 128;
    const long long n0 = (long long)blockIdx.x * 128;

    const __half* srcs[4] = {
        Ahi + bz * sA + m0 * K, Alo + bz * sA + m0 * K,
        Bhi + bz * sB + n0 * K,
        (NPASS == 3) ? (Blo + bz * sB + n0 * K) : nullptr };

    auto load_chunk = [&](int stage, int k0) {
        const uint32_t base = sb + stage * STAGE_B;
        #pragma unroll
        for (int t = 0; t < NT; ++t) {
            #pragma unroll
            for (int j = 0; j < 2; ++j) {
                int idx = tid * 2 + j;
                int row = idx >> 2;
                int ch  = idx & 3;
                cp16(tile_addr(base + t * TILE_B, row, ch),
                     srcs[t] + (long long)row * K + k0 + ch * 8);
            }
        }
        CP_COMMIT();
    };

    float acc[4][4][4];
    #pragma unroll
    for (int i = 0; i < 4; ++i)
        #pragma unroll
        for (int j = 0; j < 4; ++j)
            #pragma unroll
            for (int e = 0; e < 4; ++e) acc[i][j][e] = 0.f;

    const int NC = K >> 5;
    load_chunk(0, 0);
    load_chunk(1, BKC);

    const int lrow = lane & 15;
    const int lch  = lane >> 4;

    for (int c = 0; c < NC; ++c) {
        if (c + 1 < NC) CP_WAIT(1); else CP_WAIT(0);
        __syncthreads();
        if (c + 2 < NC) load_chunk((c + 2) % NSTAGE, (c + 2) * BKC);

        const uint32_t st  = sb + (c % NSTAGE) * STAGE_B;
        const uint32_t sAh = st;
        const uint32_t sAl = st + TILE_B;
        const uint32_t sBh = st + 2 * TILE_B;
        const uint32_t sBl = st + 3 * TILE_B;   // only valid when NPASS==3

        #pragma unroll
        for (int ks = 0; ks < 2; ++ks) {
            const int chunk = ks * 2 + lch;
            uint32_t ahi[4][4], alo[4][4];
            uint32_t bhi[4][2], blo[4][2];

            #pragma unroll
            for (int mi = 0; mi < 4; ++mi) {
                const int row = wm * 64 + mi * 16 + lrow;
                ldsm4(ahi[mi], tile_addr(sAh, row, chunk));
                ldsm4(alo[mi], tile_addr(sAl, row, chunk));
            }
            #pragma unroll
            for (int bi = 0; bi < 2; ++bi) {
                const int row = wn * 32 + bi * 16 + lrow;
                uint32_t t4[4];
                ldsm4(t4, tile_addr(sBh, row, chunk));
                bhi[bi*2][0]   = t4[0]; bhi[bi*2][1]   = t4[2];
                bhi[bi*2+1][0] = t4[1]; bhi[bi*2+1][1] = t4[3];
                if (NPASS == 3) {
                    ldsm4(t4, tile_addr(sBl, row, chunk));
                    blo[bi*2][0]   = t4[0]; blo[bi*2][1]   = t4[2];
                    blo[bi*2+1][0] = t4[1]; blo[bi*2+1][1] = t4[3];
                }
            }

            #pragma unroll
            for (int mi = 0; mi < 4; ++mi)
                #pragma unroll
                for (int ni = 0; ni < 4; ++ni) {
                    mma16816(acc[mi][ni], ahi[mi], bhi[ni]);
                    if (NPASS == 3)
                        mma16816(acc[mi][ni], ahi[mi], blo[ni]);
                    mma16816(acc[mi][ni], alo[mi], bhi[ni]);
                }
        }
        __syncthreads();
    }

    // ---- epilogue ----
    const int r1 = lane >> 2;
    const int c0 = (lane & 3) * 2;
    #pragma unroll
    for (int mi = 0; mi < 4; ++mi) {
        #pragma unroll
        for (int ni = 0; ni < 4; ++ni) {
            const long long gm = m0 + wm * 64 + mi * 16 + r1;
            const long long gn = n0 + wn * 32 + ni * 8 + c0;
            float v0 = acc[mi][ni][0], v1 = acc[mi][ni][1];
            float v2 = acc[mi][ni][2], v3 = acc[mi][ni][3];
            if (Cf) {
                float* d0 = Cf + bz * sC + gm * N + gn;
                float* d1 = Cf + bz * sC + (gm + 8) * N + gn;
                d0[0] = v0; d0[1] = v1;
                d1[0] = v2; d1[1] = v3;
            } else {
                __half h0, h1, h2, h3, l0, l1, l2, l3;
                split1(v0, h0, l0); split1(v1, h1, l1);
                split1(v2, h2, l2); split1(v3, h3, l3);
                *(__half2*)(Chi + bz * sC + gm * N + gn)       = __halves2half2(h0, h1);
                *(__half2*)(Clo + bz * sC + gm * N + gn)       = __halves2half2(l0, l1);
                *(__half2*)(Chi + bz * sC + (gm + 8) * N + gn) = __halves2half2(h2, h3);
                *(__half2*)(Clo + bz * sC + (gm + 8) * N + gn) = __halves2half2(l2, l3);
            }
        }
    }
}

// ============================================================================
extern "C" void kernel_launch(void* const* d_in, const int* in_sizes, int n_in,
                              void* d_out, int out_size)
{
    const float* ix = (const float*)d_in[0];
    const float* io = (const float*)d_in[1];
    const float* W  = (const float*)d_in[2];
    const float* bb = (const float*)d_in[3];
    float* out = (float*)d_out;

    __half *ix_hi, *ix_lo, *io_hi, *io_lo, *ioT_hi;
    __half *t_hi, *t_lo, *wt_hi, *wt_lo, *m_hi, *m_lo, *p_hi, *p_lo;
    float *s, *pv, *rv;
    cudaGetSymbolAddress((void**)&ix_hi, g_ix_hi);
    cudaGetSymbolAddress((void**)&ix_lo, g_ix_lo);
    cudaGetSymbolAddress((void**)&io_hi, g_io_hi);
    cudaGetSymbolAddress((void**)&io_lo, g_io_lo);
    cudaGetSymbolAddress((void**)&ioT_hi, g_ioT_hi);
    cudaGetSymbolAddress((void**)&t_hi, g_t_hi);
    cudaGetSymbolAddress((void**)&t_lo, g_t_lo);
    cudaGetSymbolAddress((void**)&wt_hi, g_wt_hi);
    cudaGetSymbolAddress((void**)&wt_lo, g_wt_lo);
    cudaGetSymbolAddress((void**)&m_hi, g_m_hi);
    cudaGetSymbolAddress((void**)&m_lo, g_m_lo);
    cudaGetSymbolAddress((void**)&p_hi, g_p_hi);
    cudaGetSymbolAddress((void**)&p_lo, g_p_lo);
    cudaGetSymbolAddress((void**)&s, g_s);
    cudaGetSymbolAddress((void**)&pv, g_p_vec);
    cudaGetSymbolAddress((void**)&rv, g_r);

    static bool attr_set = false;
    const int smem3 = 3 * 4 * TILE_B;   // 96 KB (NPASS=3)
    const int smem2 = 3 * 3 * TILE_B;   // 72 KB (NPASS=2)
    if (!attr_set) {
        cudaFuncSetAttribute(gemm_split<3>,
                             cudaFuncAttributeMaxDynamicSharedMemorySize, smem3);
        cudaFuncSetAttribute(gemm_split<2>,
                             cudaFuncAttributeMaxDynamicSharedMemorySize, smem2);
        attr_set = true;
    }

    // 1) splits + transposes + bias vectors
    split_f32<<<(unsigned)(MELEMS / 4 / 256), 256>>>(ix, ix_hi, ix_lo, MELEMS);
    split_f32<<<(unsigned)(MELEMS / 4 / 256), 256>>>(io, io_hi, io_lo, MELEMS);
    transpose_split<<<dim3(LSEQ / 32, DIM / 32, BATCH), dim3(32, 8)>>>(
        io, ioT_hi, (__half*)nullptr, LSEQ, DIM);
    transpose_split<<<dim3(DIM / 32, DIM / 32, 1), dim3(32, 8)>>>(
        W, wt_hi, wt_lo, DIM, DIM);                 // WT[i,k] = W[k,i]
    compute_p<<<DIM / 128, 128>>>(W, bb, pv);       // p = W^T b
    compute_r<<<(BATCH * LSEQ) / 8, 256>>>(io, pv, rv);

    // 2) M = W^T W (symmetric) -> fp16 split (1024x1024, K=1024)
    {
        dim3 g(DIM / 128, DIM / 128, 1);
        gemm_split<3><<<g, 256, smem3>>>(wt_hi, wt_lo, wt_hi, wt_lo,
                                         nullptr, m_hi, m_lo,
                                         DIM, DIM, 0, 0, 0);
    }

    // 3) t = ix @ M (symmetric) -> fp16 split (16384x1024, K=1024)
    {
        dim3 g(DIM / 128, (BATCH * LSEQ) / 128, 1);
        gemm_split<3><<<g, 256, smem3>>>(ix_hi, ix_lo, m_hi, m_lo,
                                         nullptr, t_hi, t_lo,
                                         DIM, DIM, 0, 0, 0);
    }

    // 4) scores: S[b] = t[b] @ io[b]^T -> fp32 (2048x2048, K=1024)
    {
        dim3 g(LSEQ / 128, LSEQ / 128, BATCH);
        gemm_split<3><<<g, 256, smem3>>>(t_hi, t_lo, io_hi, io_lo,
                                         s, nullptr, nullptr,
                                         DIM, LSEQ,
                                         (long long)LSEQ * DIM,
                                         (long long)LSEQ * DIM,
                                         (long long)LSEQ * LSEQ);
    }

    // 5) softmax(S + r) -> P fp16 split
    softmax_split<<<BATCH * LSEQ, 256>>>(s, rv, p_hi, p_lo, LSEQ);

    // 6) out[b] = P[b] @ ioT[b]^T -> fp32 d_out (2048x1024, K=2048), 2-pass
    {
        dim3 g(DIM / 128, LSEQ / 128, BATCH);
        gemm_split<2><<<g, 256, smem2>>>(p_hi, p_lo, ioT_hi, nullptr,
                                         out, nullptr, nullptr,
                                         LSEQ, DIM,
                                         (long long)LSEQ * LSEQ,
                                         (long long)DIM * LSEQ,
                                         (long long)LSEQ * DIM);
    }
}

// round 8
// speedup vs baseline: 1.7915x; 1.1354x over previous
#include <cuda_runtime.h>
#include <cuda_fp16.h>
#include <cstdint>
#include <math.h>

// ============================================================================
// Aligner: out = softmax((ix@W^T+b) @ (io@W^T+b)^T) @ io
// B=8, L=2048, D=1024, fp32 in/out.
// Round 8: fp16 split precision.
//   M = W^T W;  t = ix@M;  S = t@io^T (+ r[m] in softmax);  out = P@io.
//   M/t/S GEMMs: 3-pass (hi*hi + hi*lo + lo*hi)  — logit-critical.
//   out GEMM: 1-pass (Ph*ioh) — output-direct error ~4e-4, within budget.
// ============================================================================

#define BATCH 8
#define LSEQ  2048
#define DIM   1024
#define MELEMS ((size_t)BATCH * LSEQ * DIM)
#define SELEMS ((size_t)BATCH * LSEQ * LSEQ)

// ---- scratch (__device__ globals per allocation rules) ----
__device__ __half g_ix_hi[MELEMS],  g_ix_lo[MELEMS];
__device__ __half g_io_hi[MELEMS],  g_io_lo[MELEMS];
__device__ __half g_ioT_hi[MELEMS];
__device__ __half g_t_hi[MELEMS],   g_t_lo[MELEMS];
__device__ __half g_wt_hi[DIM * DIM], g_wt_lo[DIM * DIM];
__device__ __half g_m_hi[DIM * DIM],  g_m_lo[DIM * DIM];
__device__ float  g_s[SELEMS];
__device__ __half g_p_hi[SELEMS];
__device__ float  g_p_vec[DIM];                 // p = W^T b
__device__ float  g_r[(size_t)BATCH * LSEQ];    // r[b,m] = io[b,m]·p

// ============================================================================
// PTX helpers (portable only)
// ============================================================================
__device__ __forceinline__ uint32_t smem_u32(const void* p) {
    uint32_t a;
    asm("{ .reg .u64 t; cvta.to.shared.u64 t, %1; cvt.u32.u64 %0, t; }"
        : "=r"(a) : "l"(p));
    return a;
}

#define CP_COMMIT() asm volatile("cp.async.commit_group;" ::: "memory")
#define CP_WAIT(N)  asm volatile("cp.async.wait_group %0;" :: "n"(N) : "memory")

__device__ __forceinline__ void cp16(uint32_t dst, const void* src) {
    asm volatile("cp.async.cg.shared.global [%0], [%1], 16;" :: "r"(dst), "l"(src));
}

__device__ __forceinline__ void ldsm4(uint32_t* r, uint32_t addr) {
    asm volatile("ldmatrix.sync.aligned.m8n8.x4.shared.b16 {%0,%1,%2,%3}, [%4];"
                 : "=r"(r[0]), "=r"(r[1]), "=r"(r[2]), "=r"(r[3]) : "r"(addr));
}

__device__ __forceinline__ void mma16816(float* d, const uint32_t* a,
                                         const uint32_t* b) {
    asm volatile(
        "mma.sync.aligned.m16n8k16.row.col.f32.f16.f16.f32 "
        "{%0,%1,%2,%3}, {%4,%5,%6,%7}, {%8,%9}, {%0,%1,%2,%3};"
        : "+f"(d[0]), "+f"(d[1]), "+f"(d[2]), "+f"(d[3])
        : "r"(a[0]), "r"(a[1]), "r"(a[2]), "r"(a[3]), "r"(b[0]), "r"(b[1]));
}

// tile layout: [rows][64 bytes], 16B chunks swizzled: chunk ^ ((row>>1)&3)
__device__ __forceinline__ uint32_t tile_addr(uint32_t base, int row, int chunk) {
    return base + row * 64 + ((chunk ^ ((row >> 1) & 3)) << 4);
}

// ============================================================================
// Helper kernels
// ============================================================================
__device__ __forceinline__ void split1(float v, __half& h, __half& l) {
    h = __float2half(v);
    l = __float2half(v - __half2float(h));
}

__global__ void split_f32(const float* __restrict__ s,
                          __half* __restrict__ hi,
                          __half* __restrict__ lo, size_t n) {
    size_t i = ((size_t)blockIdx.x * blockDim.x + threadIdx.x) * 4;
    if (i >= n) return;
    float4 v = *(const float4*)(s + i);
    __half h0, h1, h2, h3, l0, l1, l2, l3;
    split1(v.x, h0, l0); split1(v.y, h1, l1);
    split1(v.z, h2, l2); split1(v.w, h3, l3);
    *(__half2*)(hi + i)     = __halves2half2(h0, h1);
    *(__half2*)(hi + i + 2) = __halves2half2(h2, h3);
    *(__half2*)(lo + i)     = __halves2half2(l0, l1);
    *(__half2*)(lo + i + 2) = __halves2half2(l2, l3);
}

// per-batch transpose [rows, cols] -> [cols, rows]; lo output optional
__global__ void transpose_split(const float* __restrict__ src,
                                __half* __restrict__ hiT,
                                __half* __restrict__ loT,
                                int rows, int cols) {
    __shared__ float t[32][33];
    int b = blockIdx.z;
    int r0 = blockIdx.x * 32, c0 = blockIdx.y * 32;
    const float* s = src + (size_t)b * rows * cols;
    #pragma unroll
    for (int i = 0; i < 32; i += 8)
        t[threadIdx.y + i][threadIdx.x] =
            s[(size_t)(r0 + threadIdx.y + i) * cols + c0 + threadIdx.x];
    __syncthreads();
    size_t ob = (size_t)b * rows * cols;
    #pragma unroll
    for (int i = 0; i < 32; i += 8) {
        float v = t[threadIdx.x][threadIdx.y + i];
        __half h, l;
        split1(v, h, l);
        size_t o = ob + (size_t)(c0 + threadIdx.y + i) * rows + r0 + threadIdx.x;
        hiT[o] = h;
        if (loT) loT[o] = l;
    }
}

// p[i] = sum_k b[k] * W[k,i]
__global__ void compute_p(const float* __restrict__ W,
                          const float* __restrict__ b,
                          float* __restrict__ p) {
    int i = blockIdx.x * 128 + threadIdx.x;
    float acc = 0.f;
    for (int k = 0; k < DIM; ++k)
        acc += b[k] * W[(size_t)k * DIM + i];
    p[i] = acc;
}

// r[row] = io[row,:]·p   (one warp per row)
__global__ void compute_r(const float* __restrict__ io,
                          const float* __restrict__ p,
                          float* __restrict__ r) {
    int row  = blockIdx.x * 8 + (threadIdx.x >> 5);
    int lane = threadIdx.x & 31;
    const float* src = io + (size_t)row * DIM;
    float acc = 0.f;
    for (int d = lane * 4; d < DIM; d += 128) {
        float4 v  = *(const float4*)(src + d);
        float4 pv = *(const float4*)(p + d);
        acc += v.x * pv.x + v.y * pv.y + v.z * pv.z + v.w * pv.w;
    }
    #pragma unroll
    for (int o = 16; o; o >>= 1)
        acc += __shfl_xor_sync(0xFFFFFFFFu, acc, o);
    if (lane == 0) r[row] = acc;
}

// row softmax of (S[row,:] + r[b,:]); writes fp16 hi probabilities only
__global__ void softmax_h(float* __restrict__ S,
                          const float* __restrict__ r,
                          __half* __restrict__ phi, int cols) {
    float* row = S + (size_t)blockIdx.x * cols;
    const float* rr = r + (size_t)(blockIdx.x / LSEQ) * LSEQ;
    __half* hr = phi + (size_t)blockIdx.x * cols;
    const int tid = threadIdx.x;

    float lmax = -3.0e38f;
    for (int i = tid * 4; i < cols; i += 1024) {
        float4 v = *(const float4*)(row + i);
        float4 a = *(const float4*)(rr + i);
        v.x += a.x; v.y += a.y; v.z += a.z; v.w += a.w;
        lmax = fmaxf(lmax, fmaxf(fmaxf(v.x, v.y), fmaxf(v.z, v.w)));
    }
    #pragma unroll
    for (int o = 16; o; o >>= 1)
        lmax = fmaxf(lmax, __shfl_xor_sync(0xFFFFFFFFu, lmax, o));
    __shared__ float sm[8], ss[8];
    if ((tid & 31) == 0) sm[tid >> 5] = lmax;
    __syncthreads();
    float rmax = fmaxf(fmaxf(fmaxf(sm[0], sm[1]), fmaxf(sm[2], sm[3])),
                       fmaxf(fmaxf(sm[4], sm[5]), fmaxf(sm[6], sm[7])));

    float lsum = 0.f;
    for (int i = tid * 4; i < cols; i += 1024) {
        float4 v = *(const float4*)(row + i);
        float4 a = *(const float4*)(rr + i);
        v.x = expf(v.x + a.x - rmax); v.y = expf(v.y + a.y - rmax);
        v.z = expf(v.z + a.z - rmax); v.w = expf(v.w + a.w - rmax);
        *(float4*)(row + i) = v;
        lsum += v.x + v.y + v.z + v.w;
    }
    #pragma unroll
    for (int o = 16; o; o >>= 1)
        lsum += __shfl_xor_sync(0xFFFFFFFFu, lsum, o);
    if ((tid & 31) == 0) ss[tid >> 5] = lsum;
    __syncthreads();
    float inv = 1.f / (ss[0]+ss[1]+ss[2]+ss[3]+ss[4]+ss[5]+ss[6]+ss[7]);

    for (int i = tid * 4; i < cols; i += 1024) {
        float4 v = *(const float4*)(row + i);
        __half h0 = __float2half(v.x * inv);
        __half h1 = __float2half(v.y * inv);
        __half h2 = __float2half(v.z * inv);
        __half h3 = __float2half(v.w * inv);
        *(__half2*)(hr + i)     = __halves2half2(h0, h1);
        *(__half2*)(hr + i + 2) = __halves2half2(h2, h3);
    }
}

// ============================================================================
// Split-precision HMMA GEMM, CTA 128x128, warp tile 64x32, K-chunk 32.
// 3 smem stages (prefetch depth 2), 2 CTAs/SM.
// NPASS=3: C = Ah*Bh + Ah*Bl + Al*Bh (tiles: Ah, Al, Bh, Bl)
// NPASS=1: C = Ah*Bh                 (tiles: Ah, Bh)
// ============================================================================
#define BKC 32
#define TILE_B 8192

template<int NPASS>
__global__ __launch_bounds__(256, 2)
void gemm_split(const __half* __restrict__ Ahi, const __half* __restrict__ Alo,
                const __half* __restrict__ Bhi, const __half* __restrict__ Blo,
                float* __restrict__ Cf,
                __half* __restrict__ Chi, __half* __restrict__ Clo,
                int K, int N,
                long long sA, long long sB, long long sC)
{
    constexpr int NT = (NPASS == 3) ? 4 : 2;
    constexpr int STAGE_B = NT * TILE_B;
    constexpr int NSTAGE = 3;

    extern __shared__ __align__(128) char smem[];
    const uint32_t sb = smem_u32(smem);

    const int tid  = threadIdx.x;
    const int wid  = tid >> 5;
    const int lane = tid & 31;
    const int wm   = wid >> 2;
    const int wn   = wid & 3;

    const long long bz = blockIdx.z;
    const long long m0 = (long long)blockIdx.y * 128;
    const long long n0 = (long long)blockIdx.x * 128;

    // tile order: NPASS==3 -> {Ah, Al, Bh, Bl}; NPASS==1 -> {Ah, Bh}
    const __half* srcs[4];
    srcs[0] = Ahi + bz * sA + m0 * K;
    if (NPASS == 3) {
        srcs[1] = Alo + bz * sA + m0 * K;
        srcs[2] = Bhi + bz * sB + n0 * K;
        srcs[3] = Blo + bz * sB + n0 * K;
    } else {
        srcs[1] = Bhi + bz * sB + n0 * K;
        srcs[2] = nullptr;
        srcs[3] = nullptr;
    }

    auto load_chunk = [&](int stage, int k0) {
        const uint32_t base = sb + stage * STAGE_B;
        #pragma unroll
        for (int t = 0; t < NT; ++t) {
            #pragma unroll
            for (int j = 0; j < 2; ++j) {
                int idx = tid * 2 + j;
                int row = idx >> 2;
                int ch  = idx & 3;
                cp16(tile_addr(base + t * TILE_B, row, ch),
                     srcs[t] + (long long)row * K + k0 + ch * 8);
            }
        }
        CP_COMMIT();
    };

    float acc[4][4][4];
    #pragma unroll
    for (int i = 0; i < 4; ++i)
        #pragma unroll
        for (int j = 0; j < 4; ++j)
            #pragma unroll
            for (int e = 0; e < 4; ++e) acc[i][j][e] = 0.f;

    const int NC = K >> 5;
    load_chunk(0, 0);
    load_chunk(1, BKC);

    const int lrow = lane & 15;
    const int lch  = lane >> 4;

    for (int c = 0; c < NC; ++c) {
        if (c + 1 < NC) CP_WAIT(1); else CP_WAIT(0);
        __syncthreads();
        if (c + 2 < NC) load_chunk((c + 2) % NSTAGE, (c + 2) * BKC);

        const uint32_t st  = sb + (c % NSTAGE) * STAGE_B;
        const uint32_t sAh = st;
        const uint32_t sAl = st + TILE_B;                      // NPASS==3 only
        const uint32_t sBh = st + ((NPASS == 3) ? 2 : 1) * TILE_B;
        const uint32_t sBl = st + 3 * TILE_B;                  // NPASS==3 only

        #pragma unroll
        for (int ks = 0; ks < 2; ++ks) {
            const int chunk = ks * 2 + lch;
            uint32_t ahi[4][4], alo[4][4];
            uint32_t bhi[4][2], blo[4][2];

            #pragma unroll
            for (int mi = 0; mi < 4; ++mi) {
                const int row = wm * 64 + mi * 16 + lrow;
                ldsm4(ahi[mi], tile_addr(sAh, row, chunk));
                if (NPASS == 3)
                    ldsm4(alo[mi], tile_addr(sAl, row, chunk));
            }
            #pragma unroll
            for (int bi = 0; bi < 2; ++bi) {
                const int row = wn * 32 + bi * 16 + lrow;
                uint32_t t4[4];
                ldsm4(t4, tile_addr(sBh, row, chunk));
                bhi[bi*2][0]   = t4[0]; bhi[bi*2][1]   = t4[2];
                bhi[bi*2+1][0] = t4[1]; bhi[bi*2+1][1] = t4[3];
                if (NPASS == 3) {
                    ldsm4(t4, tile_addr(sBl, row, chunk));
                    blo[bi*2][0]   = t4[0]; blo[bi*2][1]   = t4[2];
                    blo[bi*2+1][0] = t4[1]; blo[bi*2+1][1] = t4[3];
                }
            }

            #pragma unroll
            for (int mi = 0; mi < 4; ++mi)
                #pragma unroll
                for (int ni = 0; ni < 4; ++ni) {
                    mma16816(acc[mi][ni], ahi[mi], bhi[ni]);
                    if (NPASS == 3) {
                        mma16816(acc[mi][ni], ahi[mi], blo[ni]);
                        mma16816(acc[mi][ni], alo[mi], bhi[ni]);
                    }
                }
        }
        __syncthreads();
    }

    // ---- epilogue ----
    const int r1 = lane >> 2;
    const int c0 = (lane & 3) * 2;
    #pragma unroll
    for (int mi = 0; mi < 4; ++mi) {
        #pragma unroll
        for (int ni = 0; ni < 4; ++ni) {
            const long long gm = m0 + wm * 64 + mi * 16 + r1;
            const long long gn = n0 + wn * 32 + ni * 8 + c0;
            float v0 = acc[mi][ni][0], v1 = acc[mi][ni][1];
            float v2 = acc[mi][ni][2], v3 = acc[mi][ni][3];
            if (Cf) {
                float* d0 = Cf + bz * sC + gm * N + gn;
                float* d1 = Cf + bz * sC + (gm + 8) * N + gn;
                d0[0] = v0; d0[1] = v1;
                d1[0] = v2; d1[1] = v3;
            } else {
                __half h0, h1, h2, h3, l0, l1, l2, l3;
                split1(v0, h0, l0); split1(v1, h1, l1);
                split1(v2, h2, l2); split1(v3, h3, l3);
                *(__half2*)(Chi + bz * sC + gm * N + gn)       = __halves2half2(h0, h1);
                *(__half2*)(Clo + bz * sC + gm * N + gn)       = __halves2half2(l0, l1);
                *(__half2*)(Chi + bz * sC + (gm + 8) * N + gn) = __halves2half2(h2, h3);
                *(__half2*)(Clo + bz * sC + (gm + 8) * N + gn) = __halves2half2(l2, l3);
            }
        }
    }
}

// ============================================================================
extern "C" void kernel_launch(void* const* d_in, const int* in_sizes, int n_in,
                              void* d_out, int out_size)
{
    const float* ix = (const float*)d_in[0];
    const float* io = (const float*)d_in[1];
    const float* W  = (const float*)d_in[2];
    const float* bb = (const float*)d_in[3];
    float* out = (float*)d_out;

    __half *ix_hi, *ix_lo, *io_hi, *io_lo, *ioT_hi;
    __half *t_hi, *t_lo, *wt_hi, *wt_lo, *m_hi, *m_lo, *p_hi;
    float *s, *pv, *rv;
    cudaGetSymbolAddress((void**)&ix_hi, g_ix_hi);
    cudaGetSymbolAddress((void**)&ix_lo, g_ix_lo);
    cudaGetSymbolAddress((void**)&io_hi, g_io_hi);
    cudaGetSymbolAddress((void**)&io_lo, g_io_lo);
    cudaGetSymbolAddress((void**)&ioT_hi, g_ioT_hi);
    cudaGetSymbolAddress((void**)&t_hi, g_t_hi);
    cudaGetSymbolAddress((void**)&t_lo, g_t_lo);
    cudaGetSymbolAddress((void**)&wt_hi, g_wt_hi);
    cudaGetSymbolAddress((void**)&wt_lo, g_wt_lo);
    cudaGetSymbolAddress((void**)&m_hi, g_m_hi);
    cudaGetSymbolAddress((void**)&m_lo, g_m_lo);
    cudaGetSymbolAddress((void**)&p_hi, g_p_hi);
    cudaGetSymbolAddress((void**)&s, g_s);
    cudaGetSymbolAddress((void**)&pv, g_p_vec);
    cudaGetSymbolAddress((void**)&rv, g_r);

    static bool attr_set = false;
    const int smem3 = 3 * 4 * TILE_B;   // 96 KB (NPASS=3)
    const int smem1 = 3 * 2 * TILE_B;   // 48 KB (NPASS=1)
    if (!attr_set) {
        cudaFuncSetAttribute(gemm_split<3>,
                             cudaFuncAttributeMaxDynamicSharedMemorySize, smem3);
        cudaFuncSetAttribute(gemm_split<1>,
                             cudaFuncAttributeMaxDynamicSharedMemorySize, smem1);
        attr_set = true;
    }

    // 1) splits + transposes + bias vectors
    split_f32<<<(unsigned)(MELEMS / 4 / 256), 256>>>(ix, ix_hi, ix_lo, MELEMS);
    split_f32<<<(unsigned)(MELEMS / 4 / 256), 256>>>(io, io_hi, io_lo, MELEMS);
    transpose_split<<<dim3(LSEQ / 32, DIM / 32, BATCH), dim3(32, 8)>>>(
        io, ioT_hi, (__half*)nullptr, LSEQ, DIM);
    transpose_split<<<dim3(DIM / 32, DIM / 32, 1), dim3(32, 8)>>>(
        W, wt_hi, wt_lo, DIM, DIM);                 // WT[i,k] = W[k,i]
    compute_p<<<DIM / 128, 128>>>(W, bb, pv);       // p = W^T b
    compute_r<<<(BATCH * LSEQ) / 8, 256>>>(io, pv, rv);

    // 2) M = W^T W (symmetric) -> fp16 split (1024x1024, K=1024)
    {
        dim3 g(DIM / 128, DIM / 128, 1);
        gemm_split<3><<<g, 256, smem3>>>(wt_hi, wt_lo, wt_hi, wt_lo,
                                         nullptr, m_hi, m_lo,
                                         DIM, DIM, 0, 0, 0);
    }

    // 3) t = ix @ M (symmetric) -> fp16 split (16384x1024, K=1024)
    {
        dim3 g(DIM / 128, (BATCH * LSEQ) / 128, 1);
        gemm_split<3><<<g, 256, smem3>>>(ix_hi, ix_lo, m_hi, m_lo,
                                         nullptr, t_hi, t_lo,
                                         DIM, DIM, 0, 0, 0);
    }

    // 4) scores: S[b] = t[b] @ io[b]^T -> fp32 (2048x2048, K=1024)
    {
        dim3 g(LSEQ / 128, LSEQ / 128, BATCH);
        gemm_split<3><<<g, 256, smem3>>>(t_hi, t_lo, io_hi, io_lo,
                                         s, nullptr, nullptr,
                                         DIM, LSEQ,
                                         (long long)LSEQ * DIM,
                                         (long long)LSEQ * DIM,
                                         (long long)LSEQ * LSEQ);
    }

    // 5) softmax(S + r) -> P fp16 (hi only)
    softmax_h<<<BATCH * LSEQ, 256>>>(s, rv, p_hi, LSEQ);

    // 6) out[b] = P[b] @ ioT[b]^T -> fp32 d_out (2048x1024, K=2048), 1-pass
    {
        dim3 g(DIM / 128, LSEQ / 128, BATCH);
        gemm_split<1><<<g, 256, smem1>>>(p_hi, nullptr, ioT_hi, nullptr,
                                         out, nullptr, nullptr,
                                         LSEQ, DIM,
                                         (long long)LSEQ * LSEQ,
                                         (long long)DIM * LSEQ,
                                         (long long)LSEQ * DIM);
    }
}